// round 13
// baseline (speedup 1.0000x reference)
#include <cuda_runtime.h>
#include <math_constants.h>
#include <cstdint>

// Problem dims
#define BB   2048
#define II   4096
#define DD   512
#define IE_  512
#define UE_  1024
#define D1_  1024
#define D2_  512
#define D3_  256

// GEMM tiling (validated operating point — 3-stage, KT=16, PAD=20)
#define KT    16
#define APAD  20
#define BPAD  20
#define ASTG  (128 * APAD)
#define BSTG  (128 * BPAD)
#define STGF  (ASTG + BSTG)
#define GEMM_SMEM (3 * STGF * 4)    // 61440 bytes

// flags
#define F_RELU  1
#define F_BIAS  2
#define F_ROUND 4
#define F_SCALE 8

#define TAIL_CTAS 256

// ---------------- scratch (alloc-free rule: __device__ globals) ----------------
__device__ float g_rs    [II];
__device__ float g_s     [BB];
__device__ float g_umr   [(size_t)BB * II];
__device__ float g_ratedT[(size_t)DD * II];
__device__ float g_candr [(size_t)BB * DD];
__device__ float g_iw1t  [2 * IE_ * DD];
__device__ float g_iw2t  [IE_ * 2 * IE_];
__device__ float g_uw1t  [2 * UE_ * DD];
__device__ float g_uw2t  [UE_ * 2 * UE_];
__device__ float g_mw1t  [D1_ * (IE_ + UE_)];
__device__ float g_mw2t  [D2_ * D1_];
__device__ float g_mw3t  [D3_ * D2_];
__device__ float g_uf    [(size_t)BB * DD];
__device__ float g_ih1   [(size_t)BB * 2 * IE_];
__device__ float g_uh1   [(size_t)BB * 2 * UE_];
__device__ float g_xcat  [(size_t)BB * (IE_ + UE_)];
__device__ float g_x1    [(size_t)BB * D1_];
__device__ float g_x2    [(size_t)BB * D2_];
__device__ float g_part  [(size_t)4 * BB * DD];
__device__ float g_part2 [(size_t)4 * BB * DD];
// device barrier state: cnt self-resets each use; gen grows monotonically across replays
__device__ unsigned g_bcnt[8];
__device__ unsigned g_bgen[8];

// ---------------- helpers ----------------
__device__ __forceinline__ float tf32r(float x) {
    float y;
    asm("cvt.rna.tf32.f32 %0, %1;" : "=f"(y) : "f"(x));
    return y;
}
__device__ __forceinline__ void mma_tf32(float* c, const uint32_t* a, const uint32_t* b) {
    asm volatile(
        "mma.sync.aligned.m16n8k8.row.col.f32.tf32.tf32.f32 "
        "{%0,%1,%2,%3}, {%4,%5,%6,%7}, {%8,%9}, {%0,%1,%2,%3};"
        : "+f"(c[0]), "+f"(c[1]), "+f"(c[2]), "+f"(c[3])
        : "r"(a[0]), "r"(a[1]), "r"(a[2]), "r"(a[3]), "r"(b[0]), "r"(b[1]));
}
__device__ __forceinline__ uint32_t smem_u32(const void* p) {
    return (uint32_t)__cvta_generic_to_shared(p);
}
__device__ __forceinline__ void ldsm4(uint32_t* r, uint32_t a) {
    asm volatile("ldmatrix.sync.aligned.m8n8.x4.shared.b16 {%0,%1,%2,%3}, [%4];"
                 : "=r"(r[0]), "=r"(r[1]), "=r"(r[2]), "=r"(r[3]) : "r"(a));
}
__device__ __forceinline__ void cpa16(uint32_t d, const void* s) {
    asm volatile("cp.async.ca.shared.global [%0], [%1], 16;" :: "r"(d), "l"(s));
}
#define CP_COMMIT asm volatile("cp.async.commit_group;")
#define CP_WAITG1 asm volatile("cp.async.wait_group 1;")
#define CP_WAIT0  asm volatile("cp.async.wait_group 0;")

__device__ __forceinline__ unsigned ld_acq(unsigned* p) {
    unsigned v;
    asm volatile("ld.acquire.gpu.u32 %0, [%1];" : "=r"(v) : "l"(p) : "memory");
    return v;
}

// grid barrier: release-arrive + acquire-poll. Each index used ONCE per launch.
__device__ __forceinline__ void gbar(int i, unsigned nCTA) {
    __syncthreads();
    if (threadIdx.x == 0) {
        unsigned* genp = &g_bgen[i];
        const unsigned old = ld_acq(genp);
        __threadfence();                       // release: prior writes visible at L2
        const unsigned my = atomicAdd(&g_bcnt[i], 1u);
        if (my == nCTA - 1u) {
            g_bcnt[i] = 0u;                    // all arrived; safe plain reset
            __threadfence();
            atomicAdd(genp, 1u);               // release the barrier
        } else {
            while (ld_acq(genp) == old) { __nanosleep(64); }
        }
        (void)ld_acq(genp);                    // acquire for the releaser too
    }
    __syncthreads();
}

// ---------------- prep: all input-only passes in ONE kernel ----------------
__device__ __forceinline__ void dev_transpose(const float* __restrict__ in,
                                              float* __restrict__ out,
                                              int R, int C, int id, int tid) {
    __shared__ float t[32][33];
    const int bx = (id % (C / 32)) * 32;
    const int by = (id / (C / 32)) * 32;
    const int tx = tid & 31, ty = tid >> 5;
    #pragma unroll
    for (int j = 0; j < 32; j += 8)
        t[ty + j][tx] = tf32r(in[(size_t)(by + ty + j) * C + bx + tx]);
    __syncthreads();
    #pragma unroll
    for (int j = 0; j < 32; j += 8)
        out[(size_t)(bx + ty + j) * R + by + tx] = t[tx][ty + j];
}

#define NT_RATED (2048)
#define NT_IW1   (512)
#define NT_IW2   (512)
#define NT_UW1   (1024)
#define NT_UW2   (2048)
#define NT_MW1   (1536)
#define NT_MW2   (512)
#define NT_MW3   (128)
#define NB_CAND  (1024)
#define NB_RS    (512)
#define PREP_BLOCKS (NT_RATED+NT_IW1+NT_IW2+NT_UW1+NT_UW2+NT_MW1+NT_MW2+NT_MW3+NB_CAND+NB_RS)

__global__ void prep_kernel(const float* __restrict__ rated, const float* __restrict__ attw,
                            const float* __restrict__ cand,
                            const float* __restrict__ iw1, const float* __restrict__ iw2,
                            const float* __restrict__ uw1, const float* __restrict__ uw2,
                            const float* __restrict__ mw1, const float* __restrict__ mw2,
                            const float* __restrict__ mw3,
                            float* __restrict__ ratedT, float* __restrict__ candr,
                            float* __restrict__ iw1t, float* __restrict__ iw2t,
                            float* __restrict__ uw1t, float* __restrict__ uw2t,
                            float* __restrict__ mw1t, float* __restrict__ mw2t,
                            float* __restrict__ mw3t, float* __restrict__ rs) {
    int id = blockIdx.x;
    const int tid = threadIdx.x;
    if (id < NT_RATED) { dev_transpose(rated, ratedT, II, DD, id, tid); return; }
    id -= NT_RATED;
    if (id < NT_IW1) { dev_transpose(iw1, iw1t, DD, 2 * IE_, id, tid); return; }
    id -= NT_IW1;
    if (id < NT_IW2) { dev_transpose(iw2, iw2t, 2 * IE_, IE_, id, tid); return; }
    id -= NT_IW2;
    if (id < NT_UW1) { dev_transpose(uw1, uw1t, DD, 2 * UE_, id, tid); return; }
    id -= NT_UW1;
    if (id < NT_UW2) { dev_transpose(uw2, uw2t, 2 * UE_, UE_, id, tid); return; }
    id -= NT_UW2;
    if (id < NT_MW1) { dev_transpose(mw1, mw1t, IE_ + UE_, D1_, id, tid); return; }
    id -= NT_MW1;
    if (id < NT_MW2) { dev_transpose(mw2, mw2t, D1_, D2_, id, tid); return; }
    id -= NT_MW2;
    if (id < NT_MW3) { dev_transpose(mw3, mw3t, D2_, D3_, id, tid); return; }
    id -= NT_MW3;
    if (id < NB_CAND) {
        const int i = id * 256 + tid;
        float4 v = ((const float4*)cand)[i];
        v.x = tf32r(v.x); v.y = tf32r(v.y); v.z = tf32r(v.z); v.w = tf32r(v.w);
        ((float4*)candr)[i] = v;
        return;
    }
    id -= NB_CAND;
    {
        const int row  = id * 8 + (tid >> 5);
        const int lane = tid & 31;
        const float* r  = rated + (size_t)row * DD;
        const float* wr = attw + DD;
        float s = 0.f;
        #pragma unroll 4
        for (int k = lane; k < DD; k += 32) s += r[k] * wr[k];
        #pragma unroll
        for (int o = 16; o > 0; o >>= 1) s += __shfl_xor_sync(0xffffffffu, s, o);
        if (lane == 0) rs[row] = s;
    }
}

// ---------------- umstats (fused max+exp): umr = tf32(um*e); srow = 1/Z ----------------
__global__ void umstats_kernel(const float* __restrict__ um, const float* __restrict__ rs,
                               float* __restrict__ umr, float* __restrict__ srow) {
    __shared__ float sv[II];        // rs, then e in place
    __shared__ float red[256];
    const int b = blockIdx.x;
    const int tid = threadIdx.x;

    float m = -CUDART_INF_F;
    for (int i = tid; i < II / 4; i += 256) {
        float4 r4 = ((const float4*)rs)[i];
        ((float4*)sv)[i] = r4;
        m = fmaxf(m, fmaxf(fmaxf(r4.x, r4.y), fmaxf(r4.z, r4.w)));
    }
    red[tid] = m; __syncthreads();
    for (int s = 128; s > 0; s >>= 1) {
        if (tid < s) red[tid] = fmaxf(red[tid], red[tid + s]);
        __syncthreads();
    }
    m = red[0];
    __syncthreads();
    for (int i = tid; i < II; i += 256) sv[i] = __expf(sv[i] - m);
    __syncthreads();

    const float4* u4 = (const float4*)(um + (size_t)b * II);
    float4*       o4 = (float4*)(umr + (size_t)b * II);
    float z = 0.f;
    for (int i = tid; i < II / 4; i += 256) {
        float4 u = u4[i];
        float4 ev = ((const float4*)sv)[i];
        float4 o;
        o.x = tf32r(u.x * ev.x); o.y = tf32r(u.y * ev.y);
        o.z = tf32r(u.z * ev.z); o.w = tf32r(u.w * ev.w);
        if (u.x != 0.f) z += ev.x;
        if (u.y != 0.f) z += ev.y;
        if (u.z != 0.f) z += ev.z;
        if (u.w != 0.f) z += ev.w;
        o4[i] = o;
    }
    red[tid] = z; __syncthreads();
    for (int s = 128; s > 0; s >>= 1) {
        if (tid < s) red[tid] += red[tid + s];
        __syncthreads();
    }
    if (tid == 0) {
        float zz = red[0];
        srow[b] = (zz > 0.f) ? (1.f / zz) : 0.f;
    }
}

// ---------------- GEMM device body (mma.sync tf32, 3-stage cp.async) ----------------
struct GDesc {
    const float* A; const float* Wt; const float* bias; float* C;
    int M, N, K, ldc, nSplit, ctaX, ctaXY, flags;
};

__device__ __forceinline__ void dev_gemm(const GDesc d, int id) {
    extern __shared__ float smemf[];
    const float* A    = d.A;
    const float* Wt   = d.Wt;
    const float* bias = d.bias;
    float*       C    = d.C;
    const int K = d.K;
    int ldc = d.ldc;

    const int z  = id / d.ctaXY;
    const int rr = id - z * d.ctaXY;
    const int by = rr / d.ctaX;
    const int bx = rr - by * d.ctaX;

    const int kLen = K / d.nSplit;
    const int kBeg = z * kLen;
    if (d.nSplit > 1) { C += (size_t)z * d.M * d.N; ldc = d.N; }

    const int tid  = threadIdx.x;
    const int warp = tid >> 5;
    const int lane = tid & 31;
    const int g  = lane >> 2;
    const int tg = lane & 3;
    const int wm = warp >> 2;
    const int wn = warp & 3;
    const int rowBase = by * 128;
    const int colBase = bx * 128;

    const int r0  = tid >> 2;
    const int kc  = (tid & 3) * 4;
    const int r1  = r0 + 64;

    const float* Ap0 = A  + (size_t)(rowBase + r0) * K + kBeg + kc;
    const float* Ap1 = A  + (size_t)(rowBase + r1) * K + kBeg + kc;
    const float* Wp0 = Wt + (size_t)(colBase + r0) * K + kBeg + kc;
    const float* Wp1 = Wt + (size_t)(colBase + r1) * K + kBeg + kc;

    const uint32_t sBase = smem_u32(smemf);
    const uint32_t dA0 = sBase + (r0 * APAD + kc) * 4;
    const uint32_t dA1 = sBase + (r1 * APAD + kc) * 4;
    const uint32_t dB0 = sBase + (ASTG + r0 * BPAD + kc) * 4;
    const uint32_t dB1 = sBase + (ASTG + r1 * BPAD + kc) * 4;

    const int lm8 = lane & 7, sel = lane >> 3;
    const uint32_t aFragBase = sBase +
        ((wm * 64 + (sel & 1) * 8 + lm8) * APAD + (sel >> 1) * 4) * 4;
    const uint32_t bFragBase = sBase +
        (ASTG + (wn * 32 + ((lane >> 4) & 1) * 8 + lm8) * BPAD + ((lane >> 3) & 1) * 4) * 4;

    float acc[4][4][4];
    #pragma unroll
    for (int mt = 0; mt < 4; ++mt)
        #pragma unroll
        for (int nt = 0; nt < 4; ++nt)
            #pragma unroll
            for (int r = 0; r < 4; ++r) acc[mt][nt][r] = 0.f;

    const int nT = kLen / KT;

    {
        cpa16(dA0, Ap0); cpa16(dA1, Ap1); cpa16(dB0, Wp0); cpa16(dB1, Wp1);
        CP_COMMIT;
        if (nT > 1) {
            const uint32_t off = STGF * 4;
            cpa16(dA0 + off, Ap0 + KT); cpa16(dA1 + off, Ap1 + KT);
            cpa16(dB0 + off, Wp0 + KT); cpa16(dB1 + off, Wp1 + KT);
        }
        CP_COMMIT;
    }

    int cs = 0;
    for (int t = 0; t < nT; ++t) {
        CP_WAITG1;
        __syncthreads();

        if (t + 2 < nT) {
            const int is = (cs == 0) ? 2 : cs - 1;
            const uint32_t off = (uint32_t)is * STGF * 4;
            const int ko = (t + 2) * KT;
            cpa16(dA0 + off, Ap0 + ko); cpa16(dA1 + off, Ap1 + ko);
            cpa16(dB0 + off, Wp0 + ko); cpa16(dB1 + off, Wp1 + ko);
        }
        CP_COMMIT;

        const uint32_t off = (uint32_t)cs * STGF * 4;
        #pragma unroll
        for (int k8 = 0; k8 < KT; k8 += 8) {
            uint32_t af[4][4];
            uint32_t b01[4], b23[4];
            #pragma unroll
            for (int mt = 0; mt < 4; ++mt)
                ldsm4(af[mt], aFragBase + off + (mt * 16 * APAD + k8) * 4);
            ldsm4(b01, bFragBase + off + k8 * 4);
            ldsm4(b23, bFragBase + off + (16 * BPAD + k8) * 4);
            uint32_t bf[4][2] = {{b01[0], b01[1]}, {b01[2], b01[3]},
                                 {b23[0], b23[1]}, {b23[2], b23[3]}};
            #pragma unroll
            for (int mt = 0; mt < 4; ++mt)
                #pragma unroll
                for (int nt = 0; nt < 4; ++nt)
                    mma_tf32(acc[mt][nt], af[mt], bf[nt]);
        }
        cs = (cs == 2) ? 0 : cs + 1;
    }
    CP_WAIT0;

    const bool doRelu  = d.flags & F_RELU;
    const bool doBias  = d.flags & F_BIAS;
    const bool doRound = d.flags & F_ROUND;
    #pragma unroll
    for (int mt = 0; mt < 4; ++mt) {
        const int row0 = rowBase + wm * 64 + mt * 16 + g;
        #pragma unroll
        for (int nt = 0; nt < 4; ++nt) {
            const int col = colBase + wn * 32 + nt * 8 + 2 * tg;
            float b0 = 0.f, b1 = 0.f;
            if (doBias) {
                float2 bv = *(const float2*)(bias + col);
                b0 = bv.x; b1 = bv.y;
            }
            float v0 = acc[mt][nt][0] + b0, v1 = acc[mt][nt][1] + b1;
            float v2 = acc[mt][nt][2] + b0, v3 = acc[mt][nt][3] + b1;
            if (doRelu) {
                v0 = fmaxf(v0, 0.f); v1 = fmaxf(v1, 0.f);
                v2 = fmaxf(v2, 0.f); v3 = fmaxf(v3, 0.f);
            }
            if (doRound) {
                v0 = tf32r(v0); v1 = tf32r(v1); v2 = tf32r(v2); v3 = tf32r(v3);
            }
            float2 o0 = {v0, v1};
            float2 o1 = {v2, v3};
            *(float2*)(C + (size_t)row0 * ldc + col)       = o0;
            *(float2*)(C + (size_t)(row0 + 8) * ldc + col) = o1;
        }
    }
}

// ---------------- combine element op ----------------
struct CDesc {
    const float* part; const float* bias; const float* srow; float* C;
    int M, N, ldc, S, flags;
};

__device__ __forceinline__ void dev_combine_one(const CDesc& d, int idx) {
    const int nq = d.N >> 2;
    const int row = idx / nq;
    const int c0  = (idx - row * nq) * 4;
    const size_t off = (size_t)row * d.N + c0;
    float4 s = *(const float4*)(d.part + off);
    for (int z = 1; z < d.S; ++z) {
        float4 p = *(const float4*)(d.part + (size_t)z * d.M * d.N + off);
        s.x += p.x; s.y += p.y; s.z += p.z; s.w += p.w;
    }
    if (d.flags & F_SCALE) {
        float sc = d.srow[row];
        s.x *= sc; s.y *= sc; s.z *= sc; s.w *= sc;
    }
    if (d.flags & F_BIAS) {
        float4 b = *(const float4*)(d.bias + c0);
        s.x += b.x; s.y += b.y; s.z += b.z; s.w += b.w;
    }
    if (d.flags & F_RELU) {
        s.x = fmaxf(s.x, 0.f); s.y = fmaxf(s.y, 0.f);
        s.z = fmaxf(s.z, 0.f); s.w = fmaxf(s.w, 0.f);
    }
    if (d.flags & F_ROUND) {
        s.x = tf32r(s.x); s.y = tf32r(s.y); s.z = tf32r(s.z); s.w = tf32r(s.w);
    }
    *(float4*)(d.C + (size_t)row * d.ldc + c0) = s;
}

// ---------------- standalone kernels for the head ----------------
__global__ void __launch_bounds__(256, 2)
mgemm(GDesc da, GDesc db, int nA) {
    const bool ub = (int)blockIdx.x >= nA;
    dev_gemm(ub ? db : da, ub ? ((int)blockIdx.x - nA) : (int)blockIdx.x);
}

__global__ void mcombine(CDesc ca, CDesc cb, int nA, int nTotal) {
    int idx = blockIdx.x * blockDim.x + threadIdx.x;
    if (idx >= nTotal) return;
    if (idx >= nA) dev_combine_one(cb, idx - nA);
    else           dev_combine_one(ca, idx);
}

// ---------------- persistent tail: 8 phases, 7 grid barriers, 256 CTAs ----------------
__global__ void __launch_bounds__(256, 2)
tail_kernel(GDesc gUser, CDesc cItem, CDesc cUser,
            GDesc gX1, CDesc cX1,
            GDesc gX2, CDesc cX2,
            GDesc gX3,
            const float* __restrict__ part,   // x3 partials (S=8)
            const float* __restrict__ mb3,
            const float* __restrict__ mw4,
            const float* __restrict__ mb4,
            float* __restrict__ out) {
    const int tid = threadIdx.x;
    const int bid = blockIdx.x;

    // Phase 0: user_emb GEMM (splitK=2 -> part2)
    dev_gemm(gUser, bid);
    gbar(0, TAIL_CTAS);

    // Phase 1: C23 (item -> xcat[:, :512], user -> xcat[:, 512:])
    {
        const int nI = BB * IE_ / 4;
        for (int i = bid * 256 + tid; i < nI; i += TAIL_CTAS * 256)
            dev_combine_one(cItem, i);
        const int nU = BB * UE_ / 4;
        for (int i = bid * 256 + tid; i < nU; i += TAIL_CTAS * 256)
            dev_combine_one(cUser, i);
    }
    gbar(1, TAIL_CTAS);

    // Phase 2: x1 GEMM (splitK=2 -> part)
    dev_gemm(gX1, bid);
    gbar(2, TAIL_CTAS);

    // Phase 3: x1 combine
    {
        const int n = BB * D1_ / 4;
        for (int i = bid * 256 + tid; i < n; i += TAIL_CTAS * 256)
            dev_combine_one(cX1, i);
    }
    gbar(3, TAIL_CTAS);

    // Phase 4: x2 GEMM (splitK=4 -> part2)
    dev_gemm(gX2, bid);
    gbar(4, TAIL_CTAS);

    // Phase 5: x2 combine
    {
        const int n = BB * D2_ / 4;
        for (int i = bid * 256 + tid; i < n; i += TAIL_CTAS * 256)
            dev_combine_one(cX2, i);
    }
    gbar(5, TAIL_CTAS);

    // Phase 6: x3 GEMM (splitK=8 -> part)
    dev_gemm(gX3, bid);
    gbar(6, TAIL_CTAS);

    // Phase 7: final — one row per warp (8 warps x 256 CTAs = 2048 rows)
    {
        const int warp = tid >> 5;
        const int lane = tid & 31;
        const int row  = bid * 8 + warp;
        float s = 0.f;
        #pragma unroll
        for (int j = 0; j < 8; ++j) {
            const int c = lane + 32 * j;
            const size_t off = (size_t)row * D3_ + c;
            float v = part[off];
            #pragma unroll
            for (int z = 1; z < 8; ++z)
                v += part[(size_t)z * BB * D3_ + off];
            v = fmaxf(v + mb3[c], 0.f);
            s += v * mw4[c];
        }
        #pragma unroll
        for (int o = 16; o > 0; o >>= 1) s += __shfl_xor_sync(0xffffffffu, s, o);
        if (lane == 0) out[row] = s + mb4[0];
    }
}

// ---------------- launch ----------------
static inline GDesc mkg(const float* A, const float* Wt, const float* bias, float* C,
                        int M, int N, int K, int ldc, int nSplit, int flags) {
    GDesc d;
    d.A = A; d.Wt = Wt; d.bias = bias; d.C = C;
    d.M = M; d.N = N; d.K = K; d.ldc = ldc; d.nSplit = nSplit;
    d.ctaX = N / 128; d.ctaXY = (N / 128) * (M / 128); d.flags = flags;
    return d;
}
static inline int gctas(const GDesc& d) { return d.ctaXY * d.nSplit; }
static inline CDesc mkc(const float* part, const float* bias, const float* srow, float* C,
                        int M, int N, int ldc, int S, int flags) {
    CDesc d;
    d.part = part; d.bias = bias; d.srow = srow; d.C = C;
    d.M = M; d.N = N; d.ldc = ldc; d.S = S; d.flags = flags;
    return d;
}

extern "C" void kernel_launch(void* const* d_in, const int* in_sizes, int n_in,
                              void* d_out, int out_size) {
    const float* cand  = (const float*)d_in[0];
    const float* rated = (const float*)d_in[1];
    const float* um    = (const float*)d_in[2];
    const float* attw  = (const float*)d_in[3];
    // d_in[4] = att_b: cancels in masked softmax, unused.
    const float* iw1 = (const float*)d_in[5];
    const float* ib1 = (const float*)d_in[6];
    const float* iw2 = (const float*)d_in[7];
    const float* ib2 = (const float*)d_in[8];
    const float* uw1 = (const float*)d_in[9];
    const float* ub1 = (const float*)d_in[10];
    const float* uw2 = (const float*)d_in[11];
    const float* ub2 = (const float*)d_in[12];
    const float* mw1 = (const float*)d_in[13];
    const float* mb1 = (const float*)d_in[14];
    const float* mw2 = (const float*)d_in[15];
    const float* mb2 = (const float*)d_in[16];
    const float* mw3 = (const float*)d_in[17];
    const float* mb3 = (const float*)d_in[18];
    const float* mw4 = (const float*)d_in[19];
    const float* mb4 = (const float*)d_in[20];
    float* out = (float*)d_out;

    float *rs, *sB, *umr, *ratedT, *candr;
    float *iw1t, *iw2t, *uw1t, *uw2t, *mw1t, *mw2t, *mw3t;
    float *uf, *ih1, *uh1, *xcat, *x1, *x2, *part, *part2;
    cudaGetSymbolAddress((void**)&rs,     g_rs);
    cudaGetSymbolAddress((void**)&sB,     g_s);
    cudaGetSymbolAddress((void**)&umr,    g_umr);
    cudaGetSymbolAddress((void**)&ratedT, g_ratedT);
    cudaGetSymbolAddress((void**)&candr,  g_candr);
    cudaGetSymbolAddress((void**)&iw1t,   g_iw1t);
    cudaGetSymbolAddress((void**)&iw2t,   g_iw2t);
    cudaGetSymbolAddress((void**)&uw1t,   g_uw1t);
    cudaGetSymbolAddress((void**)&uw2t,   g_uw2t);
    cudaGetSymbolAddress((void**)&mw1t,   g_mw1t);
    cudaGetSymbolAddress((void**)&mw2t,   g_mw2t);
    cudaGetSymbolAddress((void**)&mw3t,   g_mw3t);
    cudaGetSymbolAddress((void**)&uf,     g_uf);
    cudaGetSymbolAddress((void**)&ih1,    g_ih1);
    cudaGetSymbolAddress((void**)&uh1,    g_uh1);
    cudaGetSymbolAddress((void**)&xcat,   g_xcat);
    cudaGetSymbolAddress((void**)&x1,     g_x1);
    cudaGetSymbolAddress((void**)&x2,     g_x2);
    cudaGetSymbolAddress((void**)&part,   g_part);
    cudaGetSymbolAddress((void**)&part2,  g_part2);

    cudaFuncSetAttribute((const void*)mgemm,
                         cudaFuncAttributeMaxDynamicSharedMemorySize, GEMM_SMEM);
    cudaFuncSetAttribute((const void*)tail_kernel,
                         cudaFuncAttributeMaxDynamicSharedMemorySize, GEMM_SMEM);

    // 1) prep
    prep_kernel<<<PREP_BLOCKS, 256>>>(rated, attw, cand, iw1, iw2, uw1, uw2, mw1, mw2, mw3,
                                      ratedT, candr, iw1t, iw2t, uw1t, uw2t,
                                      mw1t, mw2t, mw3t, rs);
    // 2) umr + srow (fused global max + exp)
    umstats_kernel<<<BB, 256>>>(um, rs, umr, sB);

    // 3) MG1: uf (splitK=4 -> part) || ih1 (splitK=2 -> part2)
    {
        GDesc a = mkg(umr,   ratedT, nullptr, part,  BB, DD,      II, 0, 4, 0);
        GDesc b = mkg(candr, iw1t,   nullptr, part2, BB, 2 * IE_, DD, 0, 2, 0);
        mgemm<<<gctas(a) + gctas(b), 256, GEMM_SMEM>>>(a, b, gctas(a));
    }
    // 4) C1: uf combine || ih1 combine
    {
        CDesc a = mkc(part,  nullptr, sB,      uf,  BB, DD,      DD,      4, F_SCALE | F_ROUND);
        CDesc b = mkc(part2, ib1,     nullptr, ih1, BB, 2 * IE_, 2 * IE_, 2, F_BIAS | F_RELU | F_ROUND);
        int nA = BB * DD / 4, nB = BB * (2 * IE_) / 4;
        mcombine<<<(nA + nB + 255) / 256, 256>>>(a, b, nA, nA + nB);
    }
    // 5) MG2: uh1 (unsplit) || item_emb (splitK=4 -> part)
    {
        GDesc a = mkg(uf,  uw1t, ub1,     uh1,  BB, 2 * UE_, DD,      2 * UE_, 1, F_RELU | F_BIAS | F_ROUND);
        GDesc b = mkg(ih1, iw2t, nullptr, part, BB, IE_,     2 * IE_, 0,       4, 0);
        mgemm<<<gctas(a) + gctas(b), 256, GEMM_SMEM>>>(a, b, gctas(a));
    }
    // 6) persistent tail: user_emb -> C23 -> x1 -> C4 -> x2 -> C5 -> x3 -> final
    {
        GDesc gUser = mkg(uh1,  uw2t, nullptr, part2, BB, UE_, 2 * UE_,   0, 2, 0);
        CDesc cItem = mkc(part,  ib2, nullptr, xcat,       BB, IE_, IE_ + UE_, 4, F_BIAS | F_RELU | F_ROUND);
        CDesc cUser = mkc(part2, ub2, nullptr, xcat + IE_, BB, UE_, IE_ + UE_, 2, F_BIAS | F_RELU | F_ROUND);
        GDesc gX1   = mkg(xcat, mw1t, nullptr, part,  BB, D1_, IE_ + UE_, 0, 2, 0);
        CDesc cX1   = mkc(part,  mb1, nullptr, x1, BB, D1_, D1_, 2, F_BIAS | F_RELU | F_ROUND);
        GDesc gX2   = mkg(x1,   mw2t, nullptr, part2, BB, D2_, D1_,      0, 4, 0);
        CDesc cX2   = mkc(part2, mb2, nullptr, x2, BB, D2_, D2_, 4, F_BIAS | F_RELU | F_ROUND);
        GDesc gX3   = mkg(x2,   mw3t, nullptr, part,  BB, D3_, D2_,      0, 8, 0);
        tail_kernel<<<TAIL_CTAS, 256, GEMM_SMEM>>>(gUser, cItem, cUser, gX1, cX1,
                                                   gX2, cX2, gX3,
                                                   part, mb3, mw4, mb4, out);
    }
}

// round 14
// speedup vs baseline: 1.0190x; 1.0190x over previous
#include <cuda_runtime.h>
#include <math_constants.h>
#include <cstdint>

// Problem dims
#define BB   2048
#define II   4096
#define DD   512
#define IE_  512
#define UE_  1024
#define D1_  1024
#define D2_  512
#define D3_  256

// GEMM tiling (validated R6/R9/R12 operating point — 3-stage, KT=16, PAD=20)
#define KT    16
#define APAD  20
#define BPAD  20
#define ASTG  (128 * APAD)
#define BSTG  (128 * BPAD)
#define STGF  (ASTG + BSTG)
#define GEMM_SMEM (3 * STGF * 4)    // 61440 bytes

// flags
#define F_RELU  1
#define F_BIAS  2
#define F_ROUND 4
#define F_SCALE 8

// ---------------- scratch (alloc-free rule: __device__ globals) ----------------
__device__ float g_rs    [II];
__device__ float g_s     [BB];
__device__ float g_umr   [(size_t)BB * II];
__device__ float g_ratedT[(size_t)DD * II];
__device__ float g_candr [(size_t)BB * DD];
__device__ float g_iw1t  [2 * IE_ * DD];
__device__ float g_iw2t  [IE_ * 2 * IE_];
__device__ float g_uw1t  [2 * UE_ * DD];
__device__ float g_uw2t  [UE_ * 2 * UE_];
__device__ float g_mw1t  [D1_ * (IE_ + UE_)];
__device__ float g_mw2t  [D2_ * D1_];
__device__ float g_mw3t  [D3_ * D2_];
__device__ float g_uf    [(size_t)BB * DD];
__device__ float g_ih1   [(size_t)BB * 2 * IE_];
__device__ float g_uh1   [(size_t)BB * 2 * UE_];
__device__ float g_xcat  [(size_t)BB * (IE_ + UE_)];
__device__ float g_x1    [(size_t)BB * D1_];
__device__ float g_x2    [(size_t)BB * D2_];
__device__ float g_part  [(size_t)4 * BB * DD];
__device__ float g_part2 [(size_t)4 * BB * DD];

// ---------------- helpers ----------------
__device__ __forceinline__ float tf32r(float x) {
    float y;
    asm("cvt.rna.tf32.f32 %0, %1;" : "=f"(y) : "f"(x));
    return y;
}
__device__ __forceinline__ void mma_tf32(float* c, const uint32_t* a, const uint32_t* b) {
    asm volatile(
        "mma.sync.aligned.m16n8k8.row.col.f32.tf32.tf32.f32 "
        "{%0,%1,%2,%3}, {%4,%5,%6,%7}, {%8,%9}, {%0,%1,%2,%3};"
        : "+f"(c[0]), "+f"(c[1]), "+f"(c[2]), "+f"(c[3])
        : "r"(a[0]), "r"(a[1]), "r"(a[2]), "r"(a[3]), "r"(b[0]), "r"(b[1]));
}
__device__ __forceinline__ uint32_t smem_u32(const void* p) {
    return (uint32_t)__cvta_generic_to_shared(p);
}
__device__ __forceinline__ void ldsm4(uint32_t* r, uint32_t a) {
    asm volatile("ldmatrix.sync.aligned.m8n8.x4.shared.b16 {%0,%1,%2,%3}, [%4];"
                 : "=r"(r[0]), "=r"(r[1]), "=r"(r[2]), "=r"(r[3]) : "r"(a));
}
__device__ __forceinline__ void cpa16(uint32_t d, const void* s) {
    asm volatile("cp.async.ca.shared.global [%0], [%1], 16;" :: "r"(d), "l"(s));
}
#define CP_COMMIT asm volatile("cp.async.commit_group;")
#define CP_WAITG1 asm volatile("cp.async.wait_group 1;")
#define CP_WAIT0  asm volatile("cp.async.wait_group 0;")

// ---------------- prep: all input-only passes in ONE kernel ----------------
__device__ __forceinline__ void dev_transpose(const float* __restrict__ in,
                                              float* __restrict__ out,
                                              int R, int C, int id, int tid) {
    __shared__ float t[32][33];
    const int bx = (id % (C / 32)) * 32;
    const int by = (id / (C / 32)) * 32;
    const int tx = tid & 31, ty = tid >> 5;
    #pragma unroll
    for (int j = 0; j < 32; j += 8)
        t[ty + j][tx] = tf32r(in[(size_t)(by + ty + j) * C + bx + tx]);
    __syncthreads();
    #pragma unroll
    for (int j = 0; j < 32; j += 8)
        out[(size_t)(bx + ty + j) * R + by + tx] = t[tx][ty + j];
}

#define NT_RATED (2048)
#define NT_IW1   (512)
#define NT_IW2   (512)
#define NT_UW1   (1024)
#define NT_UW2   (2048)
#define NT_MW1   (1536)
#define NT_MW2   (512)
#define NT_MW3   (128)
#define NB_CAND  (1024)
#define NB_RS    (512)
#define PREP_BLOCKS (NT_RATED+NT_IW1+NT_IW2+NT_UW1+NT_UW2+NT_MW1+NT_MW2+NT_MW3+NB_CAND+NB_RS)

__global__ void prep_kernel(const float* __restrict__ rated, const float* __restrict__ attw,
                            const float* __restrict__ cand,
                            const float* __restrict__ iw1, const float* __restrict__ iw2,
                            const float* __restrict__ uw1, const float* __restrict__ uw2,
                            const float* __restrict__ mw1, const float* __restrict__ mw2,
                            const float* __restrict__ mw3,
                            float* __restrict__ ratedT, float* __restrict__ candr,
                            float* __restrict__ iw1t, float* __restrict__ iw2t,
                            float* __restrict__ uw1t, float* __restrict__ uw2t,
                            float* __restrict__ mw1t, float* __restrict__ mw2t,
                            float* __restrict__ mw3t, float* __restrict__ rs) {
    int id = blockIdx.x;
    const int tid = threadIdx.x;
    if (id < NT_RATED) { dev_transpose(rated, ratedT, II, DD, id, tid); return; }
    id -= NT_RATED;
    if (id < NT_IW1) { dev_transpose(iw1, iw1t, DD, 2 * IE_, id, tid); return; }
    id -= NT_IW1;
    if (id < NT_IW2) { dev_transpose(iw2, iw2t, 2 * IE_, IE_, id, tid); return; }
    id -= NT_IW2;
    if (id < NT_UW1) { dev_transpose(uw1, uw1t, DD, 2 * UE_, id, tid); return; }
    id -= NT_UW1;
    if (id < NT_UW2) { dev_transpose(uw2, uw2t, 2 * UE_, UE_, id, tid); return; }
    id -= NT_UW2;
    if (id < NT_MW1) { dev_transpose(mw1, mw1t, IE_ + UE_, D1_, id, tid); return; }
    id -= NT_MW1;
    if (id < NT_MW2) { dev_transpose(mw2, mw2t, D1_, D2_, id, tid); return; }
    id -= NT_MW2;
    if (id < NT_MW3) { dev_transpose(mw3, mw3t, D2_, D3_, id, tid); return; }
    id -= NT_MW3;
    if (id < NB_CAND) {
        const int i = id * 256 + tid;
        float4 v = ((const float4*)cand)[i];
        v.x = tf32r(v.x); v.y = tf32r(v.y); v.z = tf32r(v.z); v.w = tf32r(v.w);
        ((float4*)candr)[i] = v;
        return;
    }
    id -= NB_CAND;
    {
        const int row  = id * 8 + (tid >> 5);
        const int lane = tid & 31;
        const float* r  = rated + (size_t)row * DD;
        const float* wr = attw + DD;
        float s = 0.f;
        #pragma unroll 4
        for (int k = lane; k < DD; k += 32) s += r[k] * wr[k];
        #pragma unroll
        for (int o = 16; o > 0; o >>= 1) s += __shfl_xor_sync(0xffffffffu, s, o);
        if (lane == 0) rs[row] = s;
    }
}

// ---------------- umstats (fused max+exp): umr = tf32(um*e); srow = 1/Z ----------------
// Per-block recompute of the global max over rs is bit-identical across blocks.
__global__ void umstats_kernel(const float* __restrict__ um, const float* __restrict__ rs,
                               float* __restrict__ umr, float* __restrict__ srow) {
    __shared__ float sv[II];        // rs, then e in place
    __shared__ float red[256];
    const int b = blockIdx.x;
    const int tid = threadIdx.x;

    float m = -CUDART_INF_F;
    for (int i = tid; i < II / 4; i += 256) {
        float4 r4 = ((const float4*)rs)[i];
        ((float4*)sv)[i] = r4;
        m = fmaxf(m, fmaxf(fmaxf(r4.x, r4.y), fmaxf(r4.z, r4.w)));
    }
    red[tid] = m; __syncthreads();
    for (int s = 128; s > 0; s >>= 1) {
        if (tid < s) red[tid] = fmaxf(red[tid], red[tid + s]);
        __syncthreads();
    }
    m = red[0];
    __syncthreads();
    for (int i = tid; i < II; i += 256) sv[i] = __expf(sv[i] - m);
    __syncthreads();

    const float4* u4 = (const float4*)(um + (size_t)b * II);
    float4*       o4 = (float4*)(umr + (size_t)b * II);
    float z = 0.f;
    for (int i = tid; i < II / 4; i += 256) {
        float4 u = u4[i];
        float4 ev = ((const float4*)sv)[i];
        float4 o;
        o.x = tf32r(u.x * ev.x); o.y = tf32r(u.y * ev.y);
        o.z = tf32r(u.z * ev.z); o.w = tf32r(u.w * ev.w);
        if (u.x != 0.f) z += ev.x;
        if (u.y != 0.f) z += ev.y;
        if (u.z != 0.f) z += ev.z;
        if (u.w != 0.f) z += ev.w;
        o4[i] = o;
    }
    red[tid] = z; __syncthreads();
    for (int s = 128; s > 0; s >>= 1) {
        if (tid < s) red[tid] += red[tid + s];
        __syncthreads();
    }
    if (tid == 0) {
        float zz = red[0];
        srow[b] = (zz > 0.f) ? (1.f / zz) : 0.f;
    }
}

// ---------------- multi-GEMM (mma.sync tf32, 3-stage cp.async) ----------------
struct GDesc {
    const float* A; const float* Wt; const float* bias; float* C;
    int M, N, K, ldc, nSplit, ctaX, ctaXY, flags;
};

__global__ void __launch_bounds__(256, 2)
mgemm(GDesc da, GDesc db, int nA) {
    extern __shared__ float smemf[];
    const bool ub = (int)blockIdx.x >= nA;
    int id = ub ? ((int)blockIdx.x - nA) : (int)blockIdx.x;
    const float* A    = ub ? db.A    : da.A;
    const float* Wt   = ub ? db.Wt   : da.Wt;
    const float* bias = ub ? db.bias : da.bias;
    float*       C    = ub ? db.C    : da.C;
    const int M      = ub ? db.M      : da.M;
    const int N      = ub ? db.N      : da.N;
    const int K      = ub ? db.K      : da.K;
    int       ldc    = ub ? db.ldc    : da.ldc;
    const int nSplit = ub ? db.nSplit : da.nSplit;
    const int ctaX   = ub ? db.ctaX   : da.ctaX;
    const int ctaXY  = ub ? db.ctaXY  : da.ctaXY;
    const int flags  = ub ? db.flags  : da.flags;

    const int z  = id / ctaXY;
    const int rr = id - z * ctaXY;
    const int by = rr / ctaX;
    const int bx = rr - by * ctaX;

    const int kLen = K / nSplit;
    const int kBeg = z * kLen;
    if (nSplit > 1) { C += (size_t)z * M * N; ldc = N; }

    const int tid  = threadIdx.x;
    const int warp = tid >> 5;
    const int lane = tid & 31;
    const int g  = lane >> 2;
    const int tg = lane & 3;
    const int wm = warp >> 2;
    const int wn = warp & 3;
    const int rowBase = by * 128;
    const int colBase = bx * 128;

    const int r0  = tid >> 2;
    const int kc  = (tid & 3) * 4;
    const int r1  = r0 + 64;

    const float* Ap0 = A  + (size_t)(rowBase + r0) * K + kBeg + kc;
    const float* Ap1 = A  + (size_t)(rowBase + r1) * K + kBeg + kc;
    const float* Wp0 = Wt + (size_t)(colBase + r0) * K + kBeg + kc;
    const float* Wp1 = Wt + (size_t)(colBase + r1) * K + kBeg + kc;

    const uint32_t sBase = smem_u32(smemf);
    const uint32_t dA0 = sBase + (r0 * APAD + kc) * 4;
    const uint32_t dA1 = sBase + (r1 * APAD + kc) * 4;
    const uint32_t dB0 = sBase + (ASTG + r0 * BPAD + kc) * 4;
    const uint32_t dB1 = sBase + (ASTG + r1 * BPAD + kc) * 4;

    const int lm8 = lane & 7, sel = lane >> 3;
    const uint32_t aFragBase = sBase +
        ((wm * 64 + (sel & 1) * 8 + lm8) * APAD + (sel >> 1) * 4) * 4;
    const uint32_t bFragBase = sBase +
        (ASTG + (wn * 32 + ((lane >> 4) & 1) * 8 + lm8) * BPAD + ((lane >> 3) & 1) * 4) * 4;

    float acc[4][4][4];
    #pragma unroll
    for (int mt = 0; mt < 4; ++mt)
        #pragma unroll
        for (int nt = 0; nt < 4; ++nt)
            #pragma unroll
            for (int r = 0; r < 4; ++r) acc[mt][nt][r] = 0.f;

    const int nT = kLen / KT;

    {
        cpa16(dA0, Ap0); cpa16(dA1, Ap1); cpa16(dB0, Wp0); cpa16(dB1, Wp1);
        CP_COMMIT;
        if (nT > 1) {
            const uint32_t off = STGF * 4;
            cpa16(dA0 + off, Ap0 + KT); cpa16(dA1 + off, Ap1 + KT);
            cpa16(dB0 + off, Wp0 + KT); cpa16(dB1 + off, Wp1 + KT);
        }
        CP_COMMIT;
    }

    int cs = 0;
    for (int t = 0; t < nT; ++t) {
        CP_WAITG1;
        __syncthreads();

        if (t + 2 < nT) {
            const int is = (cs == 0) ? 2 : cs - 1;
            const uint32_t off = (uint32_t)is * STGF * 4;
            const int ko = (t + 2) * KT;
            cpa16(dA0 + off, Ap0 + ko); cpa16(dA1 + off, Ap1 + ko);
            cpa16(dB0 + off, Wp0 + ko); cpa16(dB1 + off, Wp1 + ko);
        }
        CP_COMMIT;

        const uint32_t off = (uint32_t)cs * STGF * 4;
        #pragma unroll
        for (int k8 = 0; k8 < KT; k8 += 8) {
            uint32_t af[4][4];
            uint32_t b01[4], b23[4];
            #pragma unroll
            for (int mt = 0; mt < 4; ++mt)
                ldsm4(af[mt], aFragBase + off + (mt * 16 * APAD + k8) * 4);
            ldsm4(b01, bFragBase + off + k8 * 4);
            ldsm4(b23, bFragBase + off + (16 * BPAD + k8) * 4);
            uint32_t bf[4][2] = {{b01[0], b01[1]}, {b01[2], b01[3]},
                                 {b23[0], b23[1]}, {b23[2], b23[3]}};
            #pragma unroll
            for (int mt = 0; mt < 4; ++mt)
                #pragma unroll
                for (int nt = 0; nt < 4; ++nt)
                    mma_tf32(acc[mt][nt], af[mt], bf[nt]);
        }
        cs = (cs == 2) ? 0 : cs + 1;
    }
    CP_WAIT0;

    const bool doRelu  = flags & F_RELU;
    const bool doBias  = flags & F_BIAS;
    const bool doRound = flags & F_ROUND;
    #pragma unroll
    for (int mt = 0; mt < 4; ++mt) {
        const int row0 = rowBase + wm * 64 + mt * 16 + g;
        #pragma unroll
        for (int nt = 0; nt < 4; ++nt) {
            const int col = colBase + wn * 32 + nt * 8 + 2 * tg;
            float b0 = 0.f, b1 = 0.f;
            if (doBias) {
                float2 bv = *(const float2*)(bias + col);
                b0 = bv.x; b1 = bv.y;
            }
            float v0 = acc[mt][nt][0] + b0, v1 = acc[mt][nt][1] + b1;
            float v2 = acc[mt][nt][2] + b0, v3 = acc[mt][nt][3] + b1;
            if (doRelu) {
                v0 = fmaxf(v0, 0.f); v1 = fmaxf(v1, 0.f);
                v2 = fmaxf(v2, 0.f); v3 = fmaxf(v3, 0.f);
            }
            if (doRound) {
                v0 = tf32r(v0); v1 = tf32r(v1); v2 = tf32r(v2); v3 = tf32r(v3);
            }
            float2 o0 = {v0, v1};
            float2 o1 = {v2, v3};
            *(float2*)(C + (size_t)row0 * ldc + col)       = o0;
            *(float2*)(C + (size_t)(row0 + 8) * ldc + col) = o1;
        }
    }
}

// ---------------- multi-combine: up to two combines in one launch ----------------
struct CDesc {
    const float* part; const float* bias; const float* srow; float* C;
    int M, N, ldc, S, flags;
};

__global__ void mcombine(CDesc ca, CDesc cb, int nA, int nTotal) {
    int idx = blockIdx.x * blockDim.x + threadIdx.x;
    if (idx >= nTotal) return;
    const bool ub = idx >= nA;
    if (ub) idx -= nA;
    CDesc d = ub ? cb : ca;
    const int nq = d.N >> 2;
    const int row = idx / nq;
    const int c0  = (idx - row * nq) * 4;
    const size_t off = (size_t)row * d.N + c0;
    float4 s = *(const float4*)(d.part + off);
    for (int z = 1; z < d.S; ++z) {
        float4 p = *(const float4*)(d.part + (size_t)z * d.M * d.N + off);
        s.x += p.x; s.y += p.y; s.z += p.z; s.w += p.w;
    }
    if (d.flags & F_SCALE) {
        float sc = d.srow[row];
        s.x *= sc; s.y *= sc; s.z *= sc; s.w *= sc;
    }
    if (d.flags & F_BIAS) {
        float4 b = *(const float4*)(d.bias + c0);
        s.x += b.x; s.y += b.y; s.z += b.z; s.w += b.w;
    }
    if (d.flags & F_RELU) {
        s.x = fmaxf(s.x, 0.f); s.y = fmaxf(s.y, 0.f);
        s.z = fmaxf(s.z, 0.f); s.w = fmaxf(s.w, 0.f);
    }
    if (d.flags & F_ROUND) {
        s.x = tf32r(s.x); s.y = tf32r(s.y); s.z = tf32r(s.z); s.w = tf32r(s.w);
    }
    *(float4*)(d.C + (size_t)row * d.ldc + c0) = s;
}

// ---------------- fused: x3 combine (S=8) + final GEMV ----------------
__global__ void combine8_final(const float* __restrict__ part,
                               const float* __restrict__ mb3v,
                               const float* __restrict__ mw4,
                               const float* __restrict__ mb4,
                               float* __restrict__ out) {
    __shared__ float red[256];
    const int b = blockIdx.x;
    const int c = threadIdx.x;
    const size_t off = (size_t)b * D3_ + c;
    float v = part[off];
    #pragma unroll
    for (int z = 1; z < 8; ++z)
        v += part[(size_t)z * BB * D3_ + off];
    v = fmaxf(v + mb3v[c], 0.f);
    red[c] = v * mw4[c];
    __syncthreads();
    for (int s = 128; s > 0; s >>= 1) {
        if (c < s) red[c] += red[c + s];
        __syncthreads();
    }
    if (c == 0) out[b] = red[0] + mb4[0];
}

// ---------------- launch ----------------
static inline GDesc mkg(const float* A, const float* Wt, const float* bias, float* C,
                        int M, int N, int K, int ldc, int nSplit, int flags) {
    GDesc d;
    d.A = A; d.Wt = Wt; d.bias = bias; d.C = C;
    d.M = M; d.N = N; d.K = K; d.ldc = ldc; d.nSplit = nSplit;
    d.ctaX = N / 128; d.ctaXY = (N / 128) * (M / 128); d.flags = flags;
    return d;
}
static inline int gctas(const GDesc& d) { return d.ctaXY * d.nSplit; }
static inline CDesc mkc(const float* part, const float* bias, const float* srow, float* C,
                        int M, int N, int ldc, int S, int flags) {
    CDesc d;
    d.part = part; d.bias = bias; d.srow = srow; d.C = C;
    d.M = M; d.N = N; d.ldc = ldc; d.S = S; d.flags = flags;
    return d;
}

extern "C" void kernel_launch(void* const* d_in, const int* in_sizes, int n_in,
                              void* d_out, int out_size) {
    const float* cand  = (const float*)d_in[0];
    const float* rated = (const float*)d_in[1];
    const float* um    = (const float*)d_in[2];
    const float* attw  = (const float*)d_in[3];
    // d_in[4] = att_b: cancels in masked softmax, unused.
    const float* iw1 = (const float*)d_in[5];
    const float* ib1 = (const float*)d_in[6];
    const float* iw2 = (const float*)d_in[7];
    const float* ib2 = (const float*)d_in[8];
    const float* uw1 = (const float*)d_in[9];
    const float* ub1 = (const float*)d_in[10];
    const float* uw2 = (const float*)d_in[11];
    const float* ub2 = (const float*)d_in[12];
    const float* mw1 = (const float*)d_in[13];
    const float* mb1 = (const float*)d_in[14];
    const float* mw2 = (const float*)d_in[15];
    const float* mb2 = (const float*)d_in[16];
    const float* mw3 = (const float*)d_in[17];
    const float* mb3 = (const float*)d_in[18];
    const float* mw4 = (const float*)d_in[19];
    const float* mb4 = (const float*)d_in[20];
    float* out = (float*)d_out;

    float *rs, *sB, *umr, *ratedT, *candr;
    float *iw1t, *iw2t, *uw1t, *uw2t, *mw1t, *mw2t, *mw3t;
    float *uf, *ih1, *uh1, *xcat, *x1, *x2, *part, *part2;
    cudaGetSymbolAddress((void**)&rs,     g_rs);
    cudaGetSymbolAddress((void**)&sB,     g_s);
    cudaGetSymbolAddress((void**)&umr,    g_umr);
    cudaGetSymbolAddress((void**)&ratedT, g_ratedT);
    cudaGetSymbolAddress((void**)&candr,  g_candr);
    cudaGetSymbolAddress((void**)&iw1t,   g_iw1t);
    cudaGetSymbolAddress((void**)&iw2t,   g_iw2t);
    cudaGetSymbolAddress((void**)&uw1t,   g_uw1t);
    cudaGetSymbolAddress((void**)&uw2t,   g_uw2t);
    cudaGetSymbolAddress((void**)&mw1t,   g_mw1t);
    cudaGetSymbolAddress((void**)&mw2t,   g_mw2t);
    cudaGetSymbolAddress((void**)&mw3t,   g_mw3t);
    cudaGetSymbolAddress((void**)&uf,     g_uf);
    cudaGetSymbolAddress((void**)&ih1,    g_ih1);
    cudaGetSymbolAddress((void**)&uh1,    g_uh1);
    cudaGetSymbolAddress((void**)&xcat,   g_xcat);
    cudaGetSymbolAddress((void**)&x1,     g_x1);
    cudaGetSymbolAddress((void**)&x2,     g_x2);
    cudaGetSymbolAddress((void**)&part,   g_part);
    cudaGetSymbolAddress((void**)&part2,  g_part2);

    cudaFuncSetAttribute((const void*)mgemm,
                         cudaFuncAttributeMaxDynamicSharedMemorySize, GEMM_SMEM);

    // 1) prep
    prep_kernel<<<PREP_BLOCKS, 256>>>(rated, attw, cand, iw1, iw2, uw1, uw2, mw1, mw2, mw3,
                                      ratedT, candr, iw1t, iw2t, uw1t, uw2t,
                                      mw1t, mw2t, mw3t, rs);
    // 2) umr + srow (fused global max + exp)
    umstats_kernel<<<BB, 256>>>(um, rs, umr, sB);

    // 3) MG1: uf (splitK=4 -> part) || ih1 (splitK=2 -> part2)
    {
        GDesc a = mkg(umr,   ratedT, nullptr, part,  BB, DD,      II, 0, 4, 0);
        GDesc b = mkg(candr, iw1t,   nullptr, part2, BB, 2 * IE_, DD, 0, 2, 0);
        mgemm<<<gctas(a) + gctas(b), 256, GEMM_SMEM>>>(a, b, gctas(a));
    }
    // 4) C1: uf combine || ih1 combine
    {
        CDesc a = mkc(part,  nullptr, sB,      uf,  BB, DD,      DD,      4, F_SCALE | F_ROUND);
        CDesc b = mkc(part2, ib1,     nullptr, ih1, BB, 2 * IE_, 2 * IE_, 2, F_BIAS | F_RELU | F_ROUND);
        int nA = BB * DD / 4, nB = BB * (2 * IE_) / 4;
        mcombine<<<(nA + nB + 255) / 256, 256>>>(a, b, nA, nA + nB);
    }
    // 5) MG2: uh1 (unsplit) || item_emb (splitK=4 -> part)
    {
        GDesc a = mkg(uf,  uw1t, ub1,     uh1,  BB, 2 * UE_, DD,      2 * UE_, 1, F_RELU | F_BIAS | F_ROUND);
        GDesc b = mkg(ih1, iw2t, nullptr, part, BB, IE_,     2 * IE_, 0,       4, 0);
        mgemm<<<gctas(a) + gctas(b), 256, GEMM_SMEM>>>(a, b, gctas(a));
    }
    // 6) user_emb GEMM (splitK=2 -> part2)
    {
        GDesc a = mkg(uh1, uw2t, nullptr, part2, BB, UE_, 2 * UE_, 0, 2, 0);
        mgemm<<<gctas(a), 256, GEMM_SMEM>>>(a, a, gctas(a));
    }
    // 7) C2+C3 paired: item_emb -> xcat[:, :512] || user -> xcat[:, 512:]
    {
        CDesc a = mkc(part,  ib2, nullptr, xcat,       BB, IE_, IE_ + UE_, 4, F_BIAS | F_RELU | F_ROUND);
        CDesc b = mkc(part2, ub2, nullptr, xcat + IE_, BB, UE_, IE_ + UE_, 2, F_BIAS | F_RELU | F_ROUND);
        int nA = BB * IE_ / 4, nB = BB * UE_ / 4;
        mcombine<<<(nA + nB + 255) / 256, 256>>>(a, b, nA, nA + nB);
    }
    // 8) x1 GEMM (splitK=2 -> part)
    {
        GDesc a = mkg(xcat, mw1t, nullptr, part, BB, D1_, IE_ + UE_, 0, 2, 0);
        mgemm<<<gctas(a), 256, GEMM_SMEM>>>(a, a, gctas(a));
    }
    // 9) C4: x1 combine
    {
        CDesc a = mkc(part, mb1, nullptr, x1, BB, D1_, D1_, 2, F_BIAS | F_RELU | F_ROUND);
        int nA = BB * D1_ / 4;
        mcombine<<<(nA + 255) / 256, 256>>>(a, a, nA, nA);
    }
    // 10) x2 GEMM (splitK=4 -> part2)
    {
        GDesc a = mkg(x1, mw2t, nullptr, part2, BB, D2_, D1_, 0, 4, 0);
        mgemm<<<gctas(a), 256, GEMM_SMEM>>>(a, a, gctas(a));
    }
    // 11) C5: x2 combine
    {
        CDesc a = mkc(part2, mb2, nullptr, x2, BB, D2_, D2_, 4, F_BIAS | F_RELU | F_ROUND);
        int nA = BB * D2_ / 4;
        mcombine<<<(nA + 255) / 256, 256>>>(a, a, nA, nA);
    }
    // 12) x3 GEMM (splitK=8 -> part)
    {
        GDesc a = mkg(x2, mw3t, nullptr, part, BB, D3_, D2_, 0, 8, 0);
        mgemm<<<gctas(a), 256, GEMM_SMEM>>>(a, a, gctas(a));
    }
    // 13) fused x3 combine + final GEMV
    combine8_final<<<BB, 256>>>(part, mb3, mw4, mb4, out);
}

// round 15
// speedup vs baseline: 1.0319x; 1.0127x over previous
#include <cuda_runtime.h>
#include <math_constants.h>
#include <cstdint>

// Problem dims
#define BB   2048
#define II   4096
#define DD   512
#define IE_  512
#define UE_  1024
#define D1_  1024
#define D2_  512
#define D3_  256

// GEMM tiling (validated R6/R9/R12 operating point — 3-stage, KT=16, PAD=20)
#define KT    16
#define APAD  20
#define BPAD  20
#define ASTG  (128 * APAD)
#define BSTG  (128 * BPAD)
#define STGF  (ASTG + BSTG)
#define GEMM_SMEM (3 * STGF * 4)    // 61440 bytes

// flags
#define F_RELU  1
#define F_BIAS  2
#define F_ROUND 4
#define F_SCALE 8

// ---------------- scratch (alloc-free rule: __device__ globals) ----------------
__device__ float g_rs    [II];
__device__ float g_e     [II];
__device__ float g_s     [BB];
__device__ float g_umr   [(size_t)BB * II];
__device__ float g_ratedT[(size_t)DD * II];
__device__ float g_candr [(size_t)BB * DD];
__device__ float g_iw1t  [2 * IE_ * DD];
__device__ float g_iw2t  [IE_ * 2 * IE_];
__device__ float g_uw1t  [2 * UE_ * DD];
__device__ float g_uw2t  [UE_ * 2 * UE_];
__device__ float g_mw1t  [D1_ * (IE_ + UE_)];
__device__ float g_mw2t  [D2_ * D1_];
__device__ float g_mw3t  [D3_ * D2_];
__device__ float g_uf    [(size_t)BB * DD];
__device__ float g_ih1   [(size_t)BB * 2 * IE_];
__device__ float g_uh1   [(size_t)BB * 2 * UE_];
__device__ float g_xcat  [(size_t)BB * (IE_ + UE_)];
__device__ float g_x1    [(size_t)BB * D1_];
__device__ float g_x2    [(size_t)BB * D2_];
__device__ float g_part  [(size_t)4 * BB * DD];
__device__ float g_part2 [(size_t)4 * BB * DD];

// ---------------- helpers ----------------
__device__ __forceinline__ float tf32r(float x) {
    float y;
    asm("cvt.rna.tf32.f32 %0, %1;" : "=f"(y) : "f"(x));
    return y;
}
__device__ __forceinline__ void mma_tf32(float* c, const uint32_t* a, const uint32_t* b) {
    asm volatile(
        "mma.sync.aligned.m16n8k8.row.col.f32.tf32.tf32.f32 "
        "{%0,%1,%2,%3}, {%4,%5,%6,%7}, {%8,%9}, {%0,%1,%2,%3};"
        : "+f"(c[0]), "+f"(c[1]), "+f"(c[2]), "+f"(c[3])
        : "r"(a[0]), "r"(a[1]), "r"(a[2]), "r"(a[3]), "r"(b[0]), "r"(b[1]));
}
__device__ __forceinline__ uint32_t smem_u32(const void* p) {
    return (uint32_t)__cvta_generic_to_shared(p);
}
__device__ __forceinline__ void ldsm4(uint32_t* r, uint32_t a) {
    asm volatile("ldmatrix.sync.aligned.m8n8.x4.shared.b16 {%0,%1,%2,%3}, [%4];"
                 : "=r"(r[0]), "=r"(r[1]), "=r"(r[2]), "=r"(r[3]) : "r"(a));
}
__device__ __forceinline__ void cpa16(uint32_t d, const void* s) {
    asm volatile("cp.async.ca.shared.global [%0], [%1], 16;" :: "r"(d), "l"(s));
}
#define CP_COMMIT asm volatile("cp.async.commit_group;")
#define CP_WAITG1 asm volatile("cp.async.wait_group 1;")
#define CP_WAIT0  asm volatile("cp.async.wait_group 0;")

// ---------------- prep: all input-only passes in ONE kernel ----------------
__device__ __forceinline__ void dev_transpose(const float* __restrict__ in,
                                              float* __restrict__ out,
                                              int R, int C, int id, int tid) {
    __shared__ float t[32][33];
    const int bx = (id % (C / 32)) * 32;
    const int by = (id / (C / 32)) * 32;
    const int tx = tid & 31, ty = tid >> 5;
    #pragma unroll
    for (int j = 0; j < 32; j += 8)
        t[ty + j][tx] = tf32r(in[(size_t)(by + ty + j) * C + bx + tx]);
    __syncthreads();
    #pragma unroll
    for (int j = 0; j < 32; j += 8)
        out[(size_t)(bx + ty + j) * R + by + tx] = t[tx][ty + j];
}

#define NT_RATED (2048)
#define NT_IW1   (512)
#define NT_IW2   (512)
#define NT_UW1   (1024)
#define NT_UW2   (2048)
#define NT_MW1   (1536)
#define NT_MW2   (512)
#define NT_MW3   (128)
#define NB_CAND  (1024)
#define NB_RS    (512)
#define PREP_BLOCKS (NT_RATED+NT_IW1+NT_IW2+NT_UW1+NT_UW2+NT_MW1+NT_MW2+NT_MW3+NB_CAND+NB_RS)

__global__ void prep_kernel(const float* __restrict__ rated, const float* __restrict__ attw,
                            const float* __restrict__ cand,
                            const float* __restrict__ iw1, const float* __restrict__ iw2,
                            const float* __restrict__ uw1, const float* __restrict__ uw2,
                            const float* __restrict__ mw1, const float* __restrict__ mw2,
                            const float* __restrict__ mw3,
                            float* __restrict__ ratedT, float* __restrict__ candr,
                            float* __restrict__ iw1t, float* __restrict__ iw2t,
                            float* __restrict__ uw1t, float* __restrict__ uw2t,
                            float* __restrict__ mw1t, float* __restrict__ mw2t,
                            float* __restrict__ mw3t, float* __restrict__ rs) {
    int id = blockIdx.x;
    const int tid = threadIdx.x;
    if (id < NT_RATED) { dev_transpose(rated, ratedT, II, DD, id, tid); return; }
    id -= NT_RATED;
    if (id < NT_IW1) { dev_transpose(iw1, iw1t, DD, 2 * IE_, id, tid); return; }
    id -= NT_IW1;
    if (id < NT_IW2) { dev_transpose(iw2, iw2t, 2 * IE_, IE_, id, tid); return; }
    id -= NT_IW2;
    if (id < NT_UW1) { dev_transpose(uw1, uw1t, DD, 2 * UE_, id, tid); return; }
    id -= NT_UW1;
    if (id < NT_UW2) { dev_transpose(uw2, uw2t, 2 * UE_, UE_, id, tid); return; }
    id -= NT_UW2;
    if (id < NT_MW1) { dev_transpose(mw1, mw1t, IE_ + UE_, D1_, id, tid); return; }
    id -= NT_MW1;
    if (id < NT_MW2) { dev_transpose(mw2, mw2t, D1_, D2_, id, tid); return; }
    id -= NT_MW2;
    if (id < NT_MW3) { dev_transpose(mw3, mw3t, D2_, D3_, id, tid); return; }
    id -= NT_MW3;
    if (id < NB_CAND) {
        const int i = id * 256 + tid;
        float4 v = ((const float4*)cand)[i];
        v.x = tf32r(v.x); v.y = tf32r(v.y); v.z = tf32r(v.z); v.w = tf32r(v.w);
        ((float4*)candr)[i] = v;
        return;
    }
    id -= NB_CAND;
    {
        const int row  = id * 8 + (tid >> 5);
        const int lane = tid & 31;
        const float* r  = rated + (size_t)row * DD;
        const float* wr = attw + DD;
        float s = 0.f;
        #pragma unroll 4
        for (int k = lane; k < DD; k += 32) s += r[k] * wr[k];
        #pragma unroll
        for (int o = 16; o > 0; o >>= 1) s += __shfl_xor_sync(0xffffffffu, s, o);
        if (lane == 0) rs[row] = s;
    }
}

__global__ void maxexp_kernel(const float* __restrict__ rs, float* __restrict__ e) {
    __shared__ float red[1024];
    const int tid = threadIdx.x;
    float m = -CUDART_INF_F;
    for (int i = tid; i < II; i += 1024) m = fmaxf(m, rs[i]);
    red[tid] = m; __syncthreads();
    for (int s = 512; s > 0; s >>= 1) {
        if (tid < s) red[tid] = fmaxf(red[tid], red[tid + s]);
        __syncthreads();
    }
    m = red[0];
    for (int i = tid; i < II; i += 1024) e[i] = __expf(rs[i] - m);
}

__global__ void umstats_kernel(const float* __restrict__ um, const float* __restrict__ e,
                               float* __restrict__ umr, float* __restrict__ srow) {
    __shared__ float red[256];
    const int b = blockIdx.x;
    const int tid = threadIdx.x;
    const float4* u4 = (const float4*)(um + (size_t)b * II);
    const float4* e4 = (const float4*)e;
    float4*       o4 = (float4*)(umr + (size_t)b * II);
    float z = 0.f;
    for (int i = tid; i < II / 4; i += 256) {
        float4 u = u4[i];
        float4 ev = e4[i];
        float4 o;
        o.x = tf32r(u.x * ev.x); o.y = tf32r(u.y * ev.y);
        o.z = tf32r(u.z * ev.z); o.w = tf32r(u.w * ev.w);
        if (u.x != 0.f) z += ev.x;
        if (u.y != 0.f) z += ev.y;
        if (u.z != 0.f) z += ev.z;
        if (u.w != 0.f) z += ev.w;
        o4[i] = o;
    }
    red[tid] = z; __syncthreads();
    for (int s = 128; s > 0; s >>= 1) {
        if (tid < s) red[tid] += red[tid + s];
        __syncthreads();
    }
    if (tid == 0) {
        float zz = red[0];
        srow[b] = (zz > 0.f) ? (1.f / zz) : 0.f;
    }
}

// ---------------- multi-GEMM (mma.sync tf32, 3-stage cp.async) ----------------
struct GDesc {
    const float* A; const float* Wt; const float* bias; float* C;
    int M, N, K, ldc, nSplit, ctaX, ctaXY, flags;
};

__global__ void __launch_bounds__(256, 2)
mgemm(GDesc da, GDesc db, int nA) {
    extern __shared__ float smemf[];
    const bool ub = (int)blockIdx.x >= nA;
    int id = ub ? ((int)blockIdx.x - nA) : (int)blockIdx.x;
    const float* A    = ub ? db.A    : da.A;
    const float* Wt   = ub ? db.Wt   : da.Wt;
    const float* bias = ub ? db.bias : da.bias;
    float*       C    = ub ? db.C    : da.C;
    const int M      = ub ? db.M      : da.M;
    const int N      = ub ? db.N      : da.N;
    const int K      = ub ? db.K      : da.K;
    int       ldc    = ub ? db.ldc    : da.ldc;
    const int nSplit = ub ? db.nSplit : da.nSplit;
    const int ctaX   = ub ? db.ctaX   : da.ctaX;
    const int ctaXY  = ub ? db.ctaXY  : da.ctaXY;
    const int flags  = ub ? db.flags  : da.flags;

    const int z  = id / ctaXY;
    const int rr = id - z * ctaXY;
    const int by = rr / ctaX;
    const int bx = rr - by * ctaX;

    const int kLen = K / nSplit;
    const int kBeg = z * kLen;
    if (nSplit > 1) { C += (size_t)z * M * N; ldc = N; }

    const int tid  = threadIdx.x;
    const int warp = tid >> 5;
    const int lane = tid & 31;
    const int g  = lane >> 2;
    const int tg = lane & 3;
    const int wm = warp >> 2;
    const int wn = warp & 3;
    const int rowBase = by * 128;
    const int colBase = bx * 128;

    const int r0  = tid >> 2;
    const int kc  = (tid & 3) * 4;
    const int r1  = r0 + 64;

    const float* Ap0 = A  + (size_t)(rowBase + r0) * K + kBeg + kc;
    const float* Ap1 = A  + (size_t)(rowBase + r1) * K + kBeg + kc;
    const float* Wp0 = Wt + (size_t)(colBase + r0) * K + kBeg + kc;
    const float* Wp1 = Wt + (size_t)(colBase + r1) * K + kBeg + kc;

    const uint32_t sBase = smem_u32(smemf);
    const uint32_t dA0 = sBase + (r0 * APAD + kc) * 4;
    const uint32_t dA1 = sBase + (r1 * APAD + kc) * 4;
    const uint32_t dB0 = sBase + (ASTG + r0 * BPAD + kc) * 4;
    const uint32_t dB1 = sBase + (ASTG + r1 * BPAD + kc) * 4;

    const int lm8 = lane & 7, sel = lane >> 3;
    const uint32_t aFragBase = sBase +
        ((wm * 64 + (sel & 1) * 8 + lm8) * APAD + (sel >> 1) * 4) * 4;
    const uint32_t bFragBase = sBase +
        (ASTG + (wn * 32 + ((lane >> 4) & 1) * 8 + lm8) * BPAD + ((lane >> 3) & 1) * 4) * 4;

    float acc[4][4][4];
    #pragma unroll
    for (int mt = 0; mt < 4; ++mt)
        #pragma unroll
        for (int nt = 0; nt < 4; ++nt)
            #pragma unroll
            for (int r = 0; r < 4; ++r) acc[mt][nt][r] = 0.f;

    const int nT = kLen / KT;

    {
        cpa16(dA0, Ap0); cpa16(dA1, Ap1); cpa16(dB0, Wp0); cpa16(dB1, Wp1);
        CP_COMMIT;
        if (nT > 1) {
            const uint32_t off = STGF * 4;
            cpa16(dA0 + off, Ap0 + KT); cpa16(dA1 + off, Ap1 + KT);
            cpa16(dB0 + off, Wp0 + KT); cpa16(dB1 + off, Wp1 + KT);
        }
        CP_COMMIT;
    }

    int cs = 0;
    for (int t = 0; t < nT; ++t) {
        CP_WAITG1;
        __syncthreads();

        if (t + 2 < nT) {
            const int is = (cs == 0) ? 2 : cs - 1;
            const uint32_t off = (uint32_t)is * STGF * 4;
            const int ko = (t + 2) * KT;
            cpa16(dA0 + off, Ap0 + ko); cpa16(dA1 + off, Ap1 + ko);
            cpa16(dB0 + off, Wp0 + ko); cpa16(dB1 + off, Wp1 + ko);
        }
        CP_COMMIT;

        const uint32_t off = (uint32_t)cs * STGF * 4;
        #pragma unroll
        for (int k8 = 0; k8 < KT; k8 += 8) {
            uint32_t af[4][4];
            uint32_t b01[4], b23[4];
            #pragma unroll
            for (int mt = 0; mt < 4; ++mt)
                ldsm4(af[mt], aFragBase + off + (mt * 16 * APAD + k8) * 4);
            ldsm4(b01, bFragBase + off + k8 * 4);
            ldsm4(b23, bFragBase + off + (16 * BPAD + k8) * 4);
            uint32_t bf[4][2] = {{b01[0], b01[1]}, {b01[2], b01[3]},
                                 {b23[0], b23[1]}, {b23[2], b23[3]}};
            #pragma unroll
            for (int mt = 0; mt < 4; ++mt)
                #pragma unroll
                for (int nt = 0; nt < 4; ++nt)
                    mma_tf32(acc[mt][nt], af[mt], bf[nt]);
        }
        cs = (cs == 2) ? 0 : cs + 1;
    }
    CP_WAIT0;

    const bool doRelu  = flags & F_RELU;
    const bool doBias  = flags & F_BIAS;
    const bool doRound = flags & F_ROUND;
    #pragma unroll
    for (int mt = 0; mt < 4; ++mt) {
        const int row0 = rowBase + wm * 64 + mt * 16 + g;
        #pragma unroll
        for (int nt = 0; nt < 4; ++nt) {
            const int col = colBase + wn * 32 + nt * 8 + 2 * tg;
            float b0 = 0.f, b1 = 0.f;
            if (doBias) {
                float2 bv = *(const float2*)(bias + col);
                b0 = bv.x; b1 = bv.y;
            }
            float v0 = acc[mt][nt][0] + b0, v1 = acc[mt][nt][1] + b1;
            float v2 = acc[mt][nt][2] + b0, v3 = acc[mt][nt][3] + b1;
            if (doRelu) {
                v0 = fmaxf(v0, 0.f); v1 = fmaxf(v1, 0.f);
                v2 = fmaxf(v2, 0.f); v3 = fmaxf(v3, 0.f);
            }
            if (doRound) {
                v0 = tf32r(v0); v1 = tf32r(v1); v2 = tf32r(v2); v3 = tf32r(v3);
            }
            float2 o0 = {v0, v1};
            float2 o1 = {v2, v3};
            *(float2*)(C + (size_t)row0 * ldc + col)       = o0;
            *(float2*)(C + (size_t)(row0 + 8) * ldc + col) = o1;
        }
    }
}

// ---------------- multi-combine: up to two combines in one launch ----------------
struct CDesc {
    const float* part; const float* bias; const float* srow; float* C;
    int M, N, ldc, S, flags;
};

__global__ void mcombine(CDesc ca, CDesc cb, int nA, int nTotal) {
    int idx = blockIdx.x * blockDim.x + threadIdx.x;
    if (idx >= nTotal) return;
    const bool ub = idx >= nA;
    if (ub) idx -= nA;
    CDesc d = ub ? cb : ca;
    const int nq = d.N >> 2;
    const int row = idx / nq;
    const int c0  = (idx - row * nq) * 4;
    const size_t off = (size_t)row * d.N + c0;
    float4 s = *(const float4*)(d.part + off);
    for (int z = 1; z < d.S; ++z) {
        float4 p = *(const float4*)(d.part + (size_t)z * d.M * d.N + off);
        s.x += p.x; s.y += p.y; s.z += p.z; s.w += p.w;
    }
    if (d.flags & F_SCALE) {
        float sc = d.srow[row];
        s.x *= sc; s.y *= sc; s.z *= sc; s.w *= sc;
    }
    if (d.flags & F_BIAS) {
        float4 b = *(const float4*)(d.bias + c0);
        s.x += b.x; s.y += b.y; s.z += b.z; s.w += b.w;
    }
    if (d.flags & F_RELU) {
        s.x = fmaxf(s.x, 0.f); s.y = fmaxf(s.y, 0.f);
        s.z = fmaxf(s.z, 0.f); s.w = fmaxf(s.w, 0.f);
    }
    if (d.flags & F_ROUND) {
        s.x = tf32r(s.x); s.y = tf32r(s.y); s.z = tf32r(s.z); s.w = tf32r(s.w);
    }
    *(float4*)(d.C + (size_t)row * d.ldc + c0) = s;
}

// ---------------- fused: x3 combine (S=8) + final GEMV ----------------
__global__ void combine8_final(const float* __restrict__ part,
                               const float* __restrict__ mb3v,
                               const float* __restrict__ mw4,
                               const float* __restrict__ mb4,
                               float* __restrict__ out) {
    __shared__ float red[256];
    const int b = blockIdx.x;
    const int c = threadIdx.x;
    const size_t off = (size_t)b * D3_ + c;
    float v = part[off];
    #pragma unroll
    for (int z = 1; z < 8; ++z)
        v += part[(size_t)z * BB * D3_ + off];
    v = fmaxf(v + mb3v[c], 0.f);
    red[c] = v * mw4[c];
    __syncthreads();
    for (int s = 128; s > 0; s >>= 1) {
        if (c < s) red[c] += red[c + s];
        __syncthreads();
    }
    if (c == 0) out[b] = red[0] + mb4[0];
}

// ---------------- launch ----------------
static inline GDesc mkg(const float* A, const float* Wt, const float* bias, float* C,
                        int M, int N, int K, int ldc, int nSplit, int flags) {
    GDesc d;
    d.A = A; d.Wt = Wt; d.bias = bias; d.C = C;
    d.M = M; d.N = N; d.K = K; d.ldc = ldc; d.nSplit = nSplit;
    d.ctaX = N / 128; d.ctaXY = (N / 128) * (M / 128); d.flags = flags;
    return d;
}
static inline int gctas(const GDesc& d) { return d.ctaXY * d.nSplit; }
static inline CDesc mkc(const float* part, const float* bias, const float* srow, float* C,
                        int M, int N, int ldc, int S, int flags) {
    CDesc d;
    d.part = part; d.bias = bias; d.srow = srow; d.C = C;
    d.M = M; d.N = N; d.ldc = ldc; d.S = S; d.flags = flags;
    return d;
}

extern "C" void kernel_launch(void* const* d_in, const int* in_sizes, int n_in,
                              void* d_out, int out_size) {
    const float* cand  = (const float*)d_in[0];
    const float* rated = (const float*)d_in[1];
    const float* um    = (const float*)d_in[2];
    const float* attw  = (const float*)d_in[3];
    // d_in[4] = att_b: cancels in the masked softmax, unused.
    const float* iw1 = (const float*)d_in[5];
    const float* ib1 = (const float*)d_in[6];
    const float* iw2 = (const float*)d_in[7];
    const float* ib2 = (const float*)d_in[8];
    const float* uw1 = (const float*)d_in[9];
    const float* ub1 = (const float*)d_in[10];
    const float* uw2 = (const float*)d_in[11];
    const float* ub2 = (const float*)d_in[12];
    const float* mw1 = (const float*)d_in[13];
    const float* mb1 = (const float*)d_in[14];
    const float* mw2 = (const float*)d_in[15];
    const float* mb2 = (const float*)d_in[16];
    const float* mw3 = (const float*)d_in[17];
    const float* mb3 = (const float*)d_in[18];
    const float* mw4 = (const float*)d_in[19];
    const float* mb4 = (const float*)d_in[20];
    float* out = (float*)d_out;

    float *rs, *e, *sB, *umr, *ratedT, *candr;
    float *iw1t, *iw2t, *uw1t, *uw2t, *mw1t, *mw2t, *mw3t;
    float *uf, *ih1, *uh1, *xcat, *x1, *x2, *part, *part2;
    cudaGetSymbolAddress((void**)&rs,     g_rs);
    cudaGetSymbolAddress((void**)&e,      g_e);
    cudaGetSymbolAddress((void**)&sB,     g_s);
    cudaGetSymbolAddress((void**)&umr,    g_umr);
    cudaGetSymbolAddress((void**)&ratedT, g_ratedT);
    cudaGetSymbolAddress((void**)&candr,  g_candr);
    cudaGetSymbolAddress((void**)&iw1t,   g_iw1t);
    cudaGetSymbolAddress((void**)&iw2t,   g_iw2t);
    cudaGetSymbolAddress((void**)&uw1t,   g_uw1t);
    cudaGetSymbolAddress((void**)&uw2t,   g_uw2t);
    cudaGetSymbolAddress((void**)&mw1t,   g_mw1t);
    cudaGetSymbolAddress((void**)&mw2t,   g_mw2t);
    cudaGetSymbolAddress((void**)&mw3t,   g_mw3t);
    cudaGetSymbolAddress((void**)&uf,     g_uf);
    cudaGetSymbolAddress((void**)&ih1,    g_ih1);
    cudaGetSymbolAddress((void**)&uh1,    g_uh1);
    cudaGetSymbolAddress((void**)&xcat,   g_xcat);
    cudaGetSymbolAddress((void**)&x1,     g_x1);
    cudaGetSymbolAddress((void**)&x2,     g_x2);
    cudaGetSymbolAddress((void**)&part,   g_part);
    cudaGetSymbolAddress((void**)&part2,  g_part2);

    cudaFuncSetAttribute((const void*)mgemm,
                         cudaFuncAttributeMaxDynamicSharedMemorySize, GEMM_SMEM);

    // 1) prep
    prep_kernel<<<PREP_BLOCKS, 256>>>(rated, attw, cand, iw1, iw2, uw1, uw2, mw1, mw2, mw3,
                                      ratedT, candr, iw1t, iw2t, uw1t, uw2t,
                                      mw1t, mw2t, mw3t, rs);
    // 2) e = exp(rs - max)
    maxexp_kernel<<<1, 1024>>>(rs, e);
    // 3) umr + srow
    umstats_kernel<<<BB, 256>>>(um, e, umr, sB);

    // 4) MG1: uf (splitK=4 -> part) || ih1 (splitK=2 -> part2)
    {
        GDesc a = mkg(umr,   ratedT, nullptr, part,  BB, DD,      II, 0, 4, 0);
        GDesc b = mkg(candr, iw1t,   nullptr, part2, BB, 2 * IE_, DD, 0, 2, 0);
        mgemm<<<gctas(a) + gctas(b), 256, GEMM_SMEM>>>(a, b, gctas(a));
    }
    // 5) C1: uf combine || ih1 combine
    {
        CDesc a = mkc(part,  nullptr, sB,      uf,  BB, DD,      DD,      4, F_SCALE | F_ROUND);
        CDesc b = mkc(part2, ib1,     nullptr, ih1, BB, 2 * IE_, 2 * IE_, 2, F_BIAS | F_RELU | F_ROUND);
        int nA = BB * DD / 4, nB = BB * (2 * IE_) / 4;
        mcombine<<<(nA + nB + 255) / 256, 256>>>(a, b, nA, nA + nB);
    }
    // 6) MG2: uh1 (unsplit) || item_emb (splitK=4 -> part)
    {
        GDesc a = mkg(uf,  uw1t, ub1,     uh1,  BB, 2 * UE_, DD,      2 * UE_, 1, F_RELU | F_BIAS | F_ROUND);
        GDesc b = mkg(ih1, iw2t, nullptr, part, BB, IE_,     2 * IE_, 0,       4, 0);
        mgemm<<<gctas(a) + gctas(b), 256, GEMM_SMEM>>>(a, b, gctas(a));
    }
    // 7) user_emb GEMM (splitK=2 -> part2)
    {
        GDesc a = mkg(uh1, uw2t, nullptr, part2, BB, UE_, 2 * UE_, 0, 2, 0);
        mgemm<<<gctas(a), 256, GEMM_SMEM>>>(a, a, gctas(a));
    }
    // 8) C2+C3 paired: item_emb -> xcat[:, :512] || user -> xcat[:, 512:]
    {
        CDesc a = mkc(part,  ib2, nullptr, xcat,       BB, IE_, IE_ + UE_, 4, F_BIAS | F_RELU | F_ROUND);
        CDesc b = mkc(part2, ub2, nullptr, xcat + IE_, BB, UE_, IE_ + UE_, 2, F_BIAS | F_RELU | F_ROUND);
        int nA = BB * IE_ / 4, nB = BB * UE_ / 4;
        mcombine<<<(nA + nB + 255) / 256, 256>>>(a, b, nA, nA + nB);
    }
    // 9) x1 GEMM (splitK=2 -> part)
    {
        GDesc a = mkg(xcat, mw1t, nullptr, part, BB, D1_, IE_ + UE_, 0, 2, 0);
        mgemm<<<gctas(a), 256, GEMM_SMEM>>>(a, a, gctas(a));
    }
    // 10) C4: x1 combine
    {
        CDesc a = mkc(part, mb1, nullptr, x1, BB, D1_, D1_, 2, F_BIAS | F_RELU | F_ROUND);
        int nA = BB * D1_ / 4;
        mcombine<<<(nA + 255) / 256, 256>>>(a, a, nA, nA);
    }
    // 11) x2 GEMM (splitK=4 -> part2)
    {
        GDesc a = mkg(x1, mw2t, nullptr, part2, BB, D2_, D1_, 0, 4, 0);
        mgemm<<<gctas(a), 256, GEMM_SMEM>>>(a, a, gctas(a));
    }
    // 12) C5: x2 combine
    {
        CDesc a = mkc(part2, mb2, nullptr, x2, BB, D2_, D2_, 4, F_BIAS | F_RELU | F_ROUND);
        int nA = BB * D2_ / 4;
        mcombine<<<(nA + 255) / 256, 256>>>(a, a, nA, nA);
    }
    // 13) x3 GEMM (splitK=8 -> part)
    {
        GDesc a = mkg(x2, mw3t, nullptr, part, BB, D3_, D2_, 0, 8, 0);
        mgemm<<<gctas(a), 256, GEMM_SMEM>>>(a, a, gctas(a));
    }
    // 14) fused x3 combine + final GEMV
    combine8_final<<<BB, 256>>>(part, mb3, mw4, mb4, out);
}

// round 17
// speedup vs baseline: 1.0393x; 1.0072x over previous
#include <cuda_runtime.h>
#include <math_constants.h>
#include <cstdint>

// Problem dims
#define BB   2048
#define II   4096
#define DD   512
#define IE_  512
#define UE_  1024
#define D1_  1024
#define D2_  512
#define D3_  256

// GEMM tiling (validated operating point — 3-stage, KT=16, PAD=20)
#define KT    16
#define APAD  20
#define BPAD  20
#define ASTG  (128 * APAD)
#define BSTG  (128 * BPAD)
#define STGF  (ASTG + BSTG)
#define GEMM_SMEM (3 * STGF * 4)    // 61440 bytes

// flags
#define F_RELU  1
#define F_BIAS  2
#define F_ROUND 4
#define F_SCALE 8

// ---------------- scratch (alloc-free rule: __device__ globals) ----------------
__device__ float g_e     [II];                 // exp(rs) — unshifted (|rs| small; shift cancels)
__device__ float g_s     [BB];
__device__ float g_umr   [(size_t)BB * II];
__device__ float g_ratedT[(size_t)DD * II];
__device__ float g_candr [(size_t)BB * DD];
__device__ float g_iw1t  [2 * IE_ * DD];
__device__ float g_iw2t  [IE_ * 2 * IE_];
__device__ float g_uw1t  [2 * UE_ * DD];
__device__ float g_uw2t  [UE_ * 2 * UE_];
__device__ float g_mw1t  [D1_ * (IE_ + UE_)];
__device__ float g_mw2t  [D2_ * D1_];
__device__ float g_mw3t  [D3_ * D2_];
__device__ float g_uf    [(size_t)BB * DD];
__device__ float g_ih1   [(size_t)BB * 2 * IE_];
__device__ float g_uh1   [(size_t)BB * 2 * UE_];
__device__ float g_xcat  [(size_t)BB * (IE_ + UE_)];
__device__ float g_x1    [(size_t)BB * D1_];
__device__ float g_x2    [(size_t)BB * D2_];
__device__ float g_part  [(size_t)4 * BB * DD];
__device__ float g_part2 [(size_t)4 * BB * DD];

// ---------------- helpers ----------------
__device__ __forceinline__ float tf32r(float x) {
    float y;
    asm("cvt.rna.tf32.f32 %0, %1;" : "=f"(y) : "f"(x));
    return y;
}
__device__ __forceinline__ void mma_tf32(float* c, const uint32_t* a, const uint32_t* b) {
    asm volatile(
        "mma.sync.aligned.m16n8k8.row.col.f32.tf32.tf32.f32 "
        "{%0,%1,%2,%3}, {%4,%5,%6,%7}, {%8,%9}, {%0,%1,%2,%3};"
        : "+f"(c[0]), "+f"(c[1]), "+f"(c[2]), "+f"(c[3])
        : "r"(a[0]), "r"(a[1]), "r"(a[2]), "r"(a[3]), "r"(b[0]), "r"(b[1]));
}
__device__ __forceinline__ uint32_t smem_u32(const void* p) {
    return (uint32_t)__cvta_generic_to_shared(p);
}
__device__ __forceinline__ void ldsm4(uint32_t* r, uint32_t a) {
    asm volatile("ldmatrix.sync.aligned.m8n8.x4.shared.b16 {%0,%1,%2,%3}, [%4];"
                 : "=r"(r[0]), "=r"(r[1]), "=r"(r[2]), "=r"(r[3]) : "r"(a));
}
__device__ __forceinline__ void cpa16(uint32_t d, const void* s) {
    asm volatile("cp.async.ca.shared.global [%0], [%1], 16;" :: "r"(d), "l"(s));
}
#define CP_COMMIT asm volatile("cp.async.commit_group;")
#define CP_WAITG1 asm volatile("cp.async.wait_group 1;")
#define CP_WAIT0  asm volatile("cp.async.wait_group 0;")

// ---------------- prep: all input-only passes in ONE kernel ----------------
__device__ __forceinline__ void dev_transpose(const float* __restrict__ in,
                                              float* __restrict__ out,
                                              int R, int C, int id, int tid) {
    __shared__ float t[32][33];
    const int bx = (id % (C / 32)) * 32;
    const int by = (id / (C / 32)) * 32;
    const int tx = tid & 31, ty = tid >> 5;
    #pragma unroll
    for (int j = 0; j < 32; j += 8)
        t[ty + j][tx] = tf32r(in[(size_t)(by + ty + j) * C + bx + tx]);
    __syncthreads();
    #pragma unroll
    for (int j = 0; j < 32; j += 8)
        out[(size_t)(bx + ty + j) * R + by + tx] = t[tx][ty + j];
}

#define NT_RATED (2048)
#define NT_IW1   (512)
#define NT_IW2   (512)
#define NT_UW1   (1024)
#define NT_UW2   (2048)
#define NT_MW1   (1536)
#define NT_MW2   (512)
#define NT_MW3   (128)
#define NB_CAND  (1024)
#define NB_RS    (512)
#define PREP_BLOCKS (NT_RATED+NT_IW1+NT_IW2+NT_UW1+NT_UW2+NT_MW1+NT_MW2+NT_MW3+NB_CAND+NB_RS)

__global__ void prep_kernel(const float* __restrict__ rated, const float* __restrict__ attw,
                            const float* __restrict__ cand,
                            const float* __restrict__ iw1, const float* __restrict__ iw2,
                            const float* __restrict__ uw1, const float* __restrict__ uw2,
                            const float* __restrict__ mw1, const float* __restrict__ mw2,
                            const float* __restrict__ mw3,
                            float* __restrict__ ratedT, float* __restrict__ candr,
                            float* __restrict__ iw1t, float* __restrict__ iw2t,
                            float* __restrict__ uw1t, float* __restrict__ uw2t,
                            float* __restrict__ mw1t, float* __restrict__ mw2t,
                            float* __restrict__ mw3t, float* __restrict__ e) {
    int id = blockIdx.x;
    const int tid = threadIdx.x;
    if (id < NT_RATED) { dev_transpose(rated, ratedT, II, DD, id, tid); return; }
    id -= NT_RATED;
    if (id < NT_IW1) { dev_transpose(iw1, iw1t, DD, 2 * IE_, id, tid); return; }
    id -= NT_IW1;
    if (id < NT_IW2) { dev_transpose(iw2, iw2t, 2 * IE_, IE_, id, tid); return; }
    id -= NT_IW2;
    if (id < NT_UW1) { dev_transpose(uw1, uw1t, DD, 2 * UE_, id, tid); return; }
    id -= NT_UW1;
    if (id < NT_UW2) { dev_transpose(uw2, uw2t, 2 * UE_, UE_, id, tid); return; }
    id -= NT_UW2;
    if (id < NT_MW1) { dev_transpose(mw1, mw1t, IE_ + UE_, D1_, id, tid); return; }
    id -= NT_MW1;
    if (id < NT_MW2) { dev_transpose(mw2, mw2t, D1_, D2_, id, tid); return; }
    id -= NT_MW2;
    if (id < NT_MW3) { dev_transpose(mw3, mw3t, D2_, D3_, id, tid); return; }
    id -= NT_MW3;
    if (id < NB_CAND) {
        const int i = id * 256 + tid;
        float4 v = ((const float4*)cand)[i];
        v.x = tf32r(v.x); v.y = tf32r(v.y); v.z = tf32r(v.z); v.w = tf32r(v.w);
        ((float4*)candr)[i] = v;
        return;
    }
    id -= NB_CAND;
    {
        // rs GEMV fused with exp: e[row] = exp(rated[row,:] . att_w[D:2D]).
        // The softmax shift cancels in um*e*(1/sum masked e), so no max pass needed.
        const int row  = id * 8 + (tid >> 5);
        const int lane = tid & 31;
        const float* r  = rated + (size_t)row * DD;
        const float* wr = attw + DD;
        float s = 0.f;
        #pragma unroll 4
        for (int k = lane; k < DD; k += 32) s += r[k] * wr[k];
        #pragma unroll
        for (int o = 16; o > 0; o >>= 1) s += __shfl_xor_sync(0xffffffffu, s, o);
        if (lane == 0) e[row] = __expf(s);
    }
}

// ---------------- umstats: umr = tf32(um*e); srow = 1/sum_{um!=0} e ----------------
__global__ void umstats_kernel(const float* __restrict__ um, const float* __restrict__ e,
                               float* __restrict__ umr, float* __restrict__ srow) {
    __shared__ float red[256];
    const int b = blockIdx.x;
    const int tid = threadIdx.x;
    const float4* u4 = (const float4*)(um + (size_t)b * II);
    const float4* e4 = (const float4*)e;
    float4*       o4 = (float4*)(umr + (size_t)b * II);
    float z = 0.f;
    for (int i = tid; i < II / 4; i += 256) {
        float4 u = u4[i];
        float4 ev = e4[i];
        float4 o;
        o.x = tf32r(u.x * ev.x); o.y = tf32r(u.y * ev.y);
        o.z = tf32r(u.z * ev.z); o.w = tf32r(u.w * ev.w);
        if (u.x != 0.f) z += ev.x;
        if (u.y != 0.f) z += ev.y;
        if (u.z != 0.f) z += ev.z;
        if (u.w != 0.f) z += ev.w;
        o4[i] = o;
    }
    red[tid] = z; __syncthreads();
    for (int s = 128; s > 0; s >>= 1) {
        if (tid < s) red[tid] += red[tid + s];
        __syncthreads();
    }
    if (tid == 0) {
        float zz = red[0];
        srow[b] = (zz > 0.f) ? (1.f / zz) : 0.f;
    }
}

// ---------------- multi-GEMM (mma.sync tf32, 3-stage cp.async) ----------------
struct GDesc {
    const float* A; const float* Wt; const float* bias; float* C;
    int M, N, K, ldc, nSplit, ctaX, ctaXY, flags;
};

__global__ void __launch_bounds__(256, 2)
mgemm(GDesc da, GDesc db, int nA) {
    extern __shared__ float smemf[];
    const bool ub = (int)blockIdx.x >= nA;
    int id = ub ? ((int)blockIdx.x - nA) : (int)blockIdx.x;
    const float* A    = ub ? db.A    : da.A;
    const float* Wt   = ub ? db.Wt   : da.Wt;
    const float* bias = ub ? db.bias : da.bias;
    float*       C    = ub ? db.C    : da.C;
    const int M      = ub ? db.M      : da.M;
    const int N      = ub ? db.N      : da.N;
    const int K      = ub ? db.K      : da.K;
    int       ldc    = ub ? db.ldc    : da.ldc;
    const int nSplit = ub ? db.nSplit : da.nSplit;
    const int ctaX   = ub ? db.ctaX   : da.ctaX;
    const int ctaXY  = ub ? db.ctaXY  : da.ctaXY;
    const int flags  = ub ? db.flags  : da.flags;

    const int z  = id / ctaXY;
    const int rr = id - z * ctaXY;
    const int by = rr / ctaX;
    const int bx = rr - by * ctaX;

    const int kLen = K / nSplit;
    const int kBeg = z * kLen;
    if (nSplit > 1) { C += (size_t)z * M * N; ldc = N; }

    const int tid  = threadIdx.x;
    const int warp = tid >> 5;
    const int lane = tid & 31;
    const int g  = lane >> 2;
    const int tg = lane & 3;
    const int wm = warp >> 2;
    const int wn = warp & 3;
    const int rowBase = by * 128;
    const int colBase = bx * 128;

    const int r0  = tid >> 2;
    const int kc  = (tid & 3) * 4;
    const int r1  = r0 + 64;

    const float* Ap0 = A  + (size_t)(rowBase + r0) * K + kBeg + kc;
    const float* Ap1 = A  + (size_t)(rowBase + r1) * K + kBeg + kc;
    const float* Wp0 = Wt + (size_t)(colBase + r0) * K + kBeg + kc;
    const float* Wp1 = Wt + (size_t)(colBase + r1) * K + kBeg + kc;

    const uint32_t sBase = smem_u32(smemf);
    const uint32_t dA0 = sBase + (r0 * APAD + kc) * 4;
    const uint32_t dA1 = sBase + (r1 * APAD + kc) * 4;
    const uint32_t dB0 = sBase + (ASTG + r0 * BPAD + kc) * 4;
    const uint32_t dB1 = sBase + (ASTG + r1 * BPAD + kc) * 4;

    const int lm8 = lane & 7, sel = lane >> 3;
    const uint32_t aFragBase = sBase +
        ((wm * 64 + (sel & 1) * 8 + lm8) * APAD + (sel >> 1) * 4) * 4;
    const uint32_t bFragBase = sBase +
        (ASTG + (wn * 32 + ((lane >> 4) & 1) * 8 + lm8) * BPAD + ((lane >> 3) & 1) * 4) * 4;

    float acc[4][4][4];
    #pragma unroll
    for (int mt = 0; mt < 4; ++mt)
        #pragma unroll
        for (int nt = 0; nt < 4; ++nt)
            #pragma unroll
            for (int r = 0; r < 4; ++r) acc[mt][nt][r] = 0.f;

    const int nT = kLen / KT;

    {
        cpa16(dA0, Ap0); cpa16(dA1, Ap1); cpa16(dB0, Wp0); cpa16(dB1, Wp1);
        CP_COMMIT;
        if (nT > 1) {
            const uint32_t off = STGF * 4;
            cpa16(dA0 + off, Ap0 + KT); cpa16(dA1 + off, Ap1 + KT);
            cpa16(dB0 + off, Wp0 + KT); cpa16(dB1 + off, Wp1 + KT);
        }
        CP_COMMIT;
    }

    int cs = 0;
    for (int t = 0; t < nT; ++t) {
        CP_WAITG1;
        __syncthreads();

        if (t + 2 < nT) {
            const int is = (cs == 0) ? 2 : cs - 1;
            const uint32_t off = (uint32_t)is * STGF * 4;
            const int ko = (t + 2) * KT;
            cpa16(dA0 + off, Ap0 + ko); cpa16(dA1 + off, Ap1 + ko);
            cpa16(dB0 + off, Wp0 + ko); cpa16(dB1 + off, Wp1 + ko);
        }
        CP_COMMIT;

        const uint32_t off = (uint32_t)cs * STGF * 4;
        #pragma unroll
        for (int k8 = 0; k8 < KT; k8 += 8) {
            uint32_t af[4][4];
            uint32_t b01[4], b23[4];
            #pragma unroll
            for (int mt = 0; mt < 4; ++mt)
                ldsm4(af[mt], aFragBase + off + (mt * 16 * APAD + k8) * 4);
            ldsm4(b01, bFragBase + off + k8 * 4);
            ldsm4(b23, bFragBase + off + (16 * BPAD + k8) * 4);
            uint32_t bf[4][2] = {{b01[0], b01[1]}, {b01[2], b01[3]},
                                 {b23[0], b23[1]}, {b23[2], b23[3]}};
            #pragma unroll
            for (int mt = 0; mt < 4; ++mt)
                #pragma unroll
                for (int nt = 0; nt < 4; ++nt)
                    mma_tf32(acc[mt][nt], af[mt], bf[nt]);
        }
        cs = (cs == 2) ? 0 : cs + 1;
    }
    CP_WAIT0;

    const bool doRelu  = flags & F_RELU;
    const bool doBias  = flags & F_BIAS;
    const bool doRound = flags & F_ROUND;
    #pragma unroll
    for (int mt = 0; mt < 4; ++mt) {
        const int row0 = rowBase + wm * 64 + mt * 16 + g;
        #pragma unroll
        for (int nt = 0; nt < 4; ++nt) {
            const int col = colBase + wn * 32 + nt * 8 + 2 * tg;
            float b0 = 0.f, b1 = 0.f;
            if (doBias) {
                float2 bv = *(const float2*)(bias + col);
                b0 = bv.x; b1 = bv.y;
            }
            float v0 = acc[mt][nt][0] + b0, v1 = acc[mt][nt][1] + b1;
            float v2 = acc[mt][nt][2] + b0, v3 = acc[mt][nt][3] + b1;
            if (doRelu) {
                v0 = fmaxf(v0, 0.f); v1 = fmaxf(v1, 0.f);
                v2 = fmaxf(v2, 0.f); v3 = fmaxf(v3, 0.f);
            }
            if (doRound) {
                v0 = tf32r(v0); v1 = tf32r(v1); v2 = tf32r(v2); v3 = tf32r(v3);
            }
            float2 o0 = {v0, v1};
            float2 o1 = {v2, v3};
            *(float2*)(C + (size_t)row0 * ldc + col)       = o0;
            *(float2*)(C + (size_t)(row0 + 8) * ldc + col) = o1;
        }
    }
}

// ---------------- multi-combine: up to two combines in one launch ----------------
struct CDesc {
    const float* part; const float* bias; const float* srow; float* C;
    int M, N, ldc, S, flags;
};

__global__ void mcombine(CDesc ca, CDesc cb, int nA, int nTotal) {
    int idx = blockIdx.x * blockDim.x + threadIdx.x;
    if (idx >= nTotal) return;
    const bool ub = idx >= nA;
    if (ub) idx -= nA;
    CDesc d = ub ? cb : ca;
    const int nq = d.N >> 2;
    const int row = idx / nq;
    const int c0  = (idx - row * nq) * 4;
    const size_t off = (size_t)row * d.N + c0;
    float4 s = *(const float4*)(d.part + off);
    for (int z = 1; z < d.S; ++z) {
        float4 p = *(const float4*)(d.part + (size_t)z * d.M * d.N + off);
        s.x += p.x; s.y += p.y; s.z += p.z; s.w += p.w;
    }
    if (d.flags & F_SCALE) {
        float sc = d.srow[row];
        s.x *= sc; s.y *= sc; s.z *= sc; s.w *= sc;
    }
    if (d.flags & F_BIAS) {
        float4 b = *(const float4*)(d.bias + c0);
        s.x += b.x; s.y += b.y; s.z += b.z; s.w += b.w;
    }
    if (d.flags & F_RELU) {
        s.x = fmaxf(s.x, 0.f); s.y = fmaxf(s.y, 0.f);
        s.z = fmaxf(s.z, 0.f); s.w = fmaxf(s.w, 0.f);
    }
    if (d.flags & F_ROUND) {
        s.x = tf32r(s.x); s.y = tf32r(s.y); s.z = tf32r(s.z); s.w = tf32r(s.w);
    }
    *(float4*)(d.C + (size_t)row * d.ldc + c0) = s;
}

// ---------------- fused: x3 combine (S=8) + final GEMV ----------------
__global__ void combine8_final(const float* __restrict__ part,
                               const float* __restrict__ mb3v,
                               const float* __restrict__ mw4,
                               const float* __restrict__ mb4,
                               float* __restrict__ out) {
    __shared__ float red[256];
    const int b = blockIdx.x;
    const int c = threadIdx.x;
    const size_t off = (size_t)b * D3_ + c;
    float v = part[off];
    #pragma unroll
    for (int z = 1; z < 8; ++z)
        v += part[(size_t)z * BB * D3_ + off];
    v = fmaxf(v + mb3v[c], 0.f);
    red[c] = v * mw4[c];
    __syncthreads();
    for (int s = 128; s > 0; s >>= 1) {
        if (c < s) red[c] += red[c + s];
        __syncthreads();
    }
    if (c == 0) out[b] = red[0] + mb4[0];
}

// ---------------- launch ----------------
static inline GDesc mkg(const float* A, const float* Wt, const float* bias, float* C,
                        int M, int N, int K, int ldc, int nSplit, int flags) {
    GDesc d;
    d.A = A; d.Wt = Wt; d.bias = bias; d.C = C;
    d.M = M; d.N = N; d.K = K; d.ldc = ldc; d.nSplit = nSplit;
    d.ctaX = N / 128; d.ctaXY = (N / 128) * (M / 128); d.flags = flags;
    return d;
}
static inline int gctas(const GDesc& d) { return d.ctaXY * d.nSplit; }
static inline CDesc mkc(const float* part, const float* bias, const float* srow, float* C,
                        int M, int N, int ldc, int S, int flags) {
    CDesc d;
    d.part = part; d.bias = bias; d.srow = srow; d.C = C;
    d.M = M; d.N = N; d.ldc = ldc; d.S = S; d.flags = flags;
    return d;
}

extern "C" void kernel_launch(void* const* d_in, const int* in_sizes, int n_in,
                              void* d_out, int out_size) {
    const float* cand  = (const float*)d_in[0];
    const float* rated = (const float*)d_in[1];
    const float* um    = (const float*)d_in[2];
    const float* attw  = (const float*)d_in[3];
    // d_in[4] = att_b: cancels in the masked softmax, unused.
    const float* iw1 = (const float*)d_in[5];
    const float* ib1 = (const float*)d_in[6];
    const float* iw2 = (const float*)d_in[7];
    const float* ib2 = (const float*)d_in[8];
    const float* uw1 = (const float*)d_in[9];
    const float* ub1 = (const float*)d_in[10];
    const float* uw2 = (const float*)d_in[11];
    const float* ub2 = (const float*)d_in[12];
    const float* mw1 = (const float*)d_in[13];
    const float* mb1 = (const float*)d_in[14];
    const float* mw2 = (const float*)d_in[15];
    const float* mb2 = (const float*)d_in[16];
    const float* mw3 = (const float*)d_in[17];
    const float* mb3 = (const float*)d_in[18];
    const float* mw4 = (const float*)d_in[19];
    const float* mb4 = (const float*)d_in[20];
    float* out = (float*)d_out;

    float *e, *sB, *umr, *ratedT, *candr;
    float *iw1t, *iw2t, *uw1t, *uw2t, *mw1t, *mw2t, *mw3t;
    float *uf, *ih1, *uh1, *xcat, *x1, *x2, *part, *part2;
    cudaGetSymbolAddress((void**)&e,      g_e);
    cudaGetSymbolAddress((void**)&sB,     g_s);
    cudaGetSymbolAddress((void**)&umr,    g_umr);
    cudaGetSymbolAddress((void**)&ratedT, g_ratedT);
    cudaGetSymbolAddress((void**)&candr,  g_candr);
    cudaGetSymbolAddress((void**)&iw1t,   g_iw1t);
    cudaGetSymbolAddress((void**)&iw2t,   g_iw2t);
    cudaGetSymbolAddress((void**)&uw1t,   g_uw1t);
    cudaGetSymbolAddress((void**)&uw2t,   g_uw2t);
    cudaGetSymbolAddress((void**)&mw1t,   g_mw1t);
    cudaGetSymbolAddress((void**)&mw2t,   g_mw2t);
    cudaGetSymbolAddress((void**)&mw3t,   g_mw3t);
    cudaGetSymbolAddress((void**)&uf,     g_uf);
    cudaGetSymbolAddress((void**)&ih1,    g_ih1);
    cudaGetSymbolAddress((void**)&uh1,    g_uh1);
    cudaGetSymbolAddress((void**)&xcat,   g_xcat);
    cudaGetSymbolAddress((void**)&x1,     g_x1);
    cudaGetSymbolAddress((void**)&x2,     g_x2);
    cudaGetSymbolAddress((void**)&part,   g_part);
    cudaGetSymbolAddress((void**)&part2,  g_part2);

    cudaFuncSetAttribute((const void*)mgemm,
                         cudaFuncAttributeMaxDynamicSharedMemorySize, GEMM_SMEM);

    // 1) prep (transposes + cand round + fused rs->exp)
    prep_kernel<<<PREP_BLOCKS, 256>>>(rated, attw, cand, iw1, iw2, uw1, uw2, mw1, mw2, mw3,
                                      ratedT, candr, iw1t, iw2t, uw1t, uw2t,
                                      mw1t, mw2t, mw3t, e);
    // 2) umr + srow
    umstats_kernel<<<BB, 256>>>(um, e, umr, sB);

    // 3) MG1: uf (splitK=4 -> part) || ih1 (splitK=2 -> part2)
    {
        GDesc a = mkg(umr,   ratedT, nullptr, part,  BB, DD,      II, 0, 4, 0);
        GDesc b = mkg(candr, iw1t,   nullptr, part2, BB, 2 * IE_, DD, 0, 2, 0);
        mgemm<<<gctas(a) + gctas(b), 256, GEMM_SMEM>>>(a, b, gctas(a));
    }
    // 4) C1: uf combine || ih1 combine
    {
        CDesc a = mkc(part,  nullptr, sB,      uf,  BB, DD,      DD,      4, F_SCALE | F_ROUND);
        CDesc b = mkc(part2, ib1,     nullptr, ih1, BB, 2 * IE_, 2 * IE_, 2, F_BIAS | F_RELU | F_ROUND);
        int nA = BB * DD / 4, nB = BB * (2 * IE_) / 4;
        mcombine<<<(nA + nB + 255) / 256, 256>>>(a, b, nA, nA + nB);
    }
    // 5) MG2: uh1 (unsplit) || item_emb (splitK=4 -> part)
    {
        GDesc a = mkg(uf,  uw1t, ub1,     uh1,  BB, 2 * UE_, DD,      2 * UE_, 1, F_RELU | F_BIAS | F_ROUND);
        GDesc b = mkg(ih1, iw2t, nullptr, part, BB, IE_,     2 * IE_, 0,       4, 0);
        mgemm<<<gctas(a) + gctas(b), 256, GEMM_SMEM>>>(a, b, gctas(a));
    }
    // 6) user_emb GEMM (splitK=2 -> part2)
    {
        GDesc a = mkg(uh1, uw2t, nullptr, part2, BB, UE_, 2 * UE_, 0, 2, 0);
        mgemm<<<gctas(a), 256, GEMM_SMEM>>>(a, a, gctas(a));
    }
    // 7) C2+C3 paired: item_emb -> xcat[:, :512] || user -> xcat[:, 512:]
    {
        CDesc a = mkc(part,  ib2, nullptr, xcat,       BB, IE_, IE_ + UE_, 4, F_BIAS | F_RELU | F_ROUND);
        CDesc b = mkc(part2, ub2, nullptr, xcat + IE_, BB, UE_, IE_ + UE_, 2, F_BIAS | F_RELU | F_ROUND);
        int nA = BB * IE_ / 4, nB = BB * UE_ / 4;
        mcombine<<<(nA + nB + 255) / 256, 256>>>(a, b, nA, nA + nB);
    }
    // 8) x1 GEMM (splitK=2 -> part)
    {
        GDesc a = mkg(xcat, mw1t, nullptr, part, BB, D1_, IE_ + UE_, 0, 2, 0);
        mgemm<<<gctas(a), 256, GEMM_SMEM>>>(a, a, gctas(a));
    }
    // 9) C4: x1 combine
    {
        CDesc a = mkc(part, mb1, nullptr, x1, BB, D1_, D1_, 2, F_BIAS | F_RELU | F_ROUND);
        int nA = BB * D1_ / 4;
        mcombine<<<(nA + 255) / 256, 256>>>(a, a, nA, nA);
    }
    // 10) x2 GEMM (splitK=4 -> part2)
    {
        GDesc a = mkg(x1, mw2t, nullptr, part2, BB, D2_, D1_, 0, 4, 0);
        mgemm<<<gctas(a), 256, GEMM_SMEM>>>(a, a, gctas(a));
    }
    // 11) C5: x2 combine
    {
        CDesc a = mkc(part2, mb2, nullptr, x2, BB, D2_, D2_, 4, F_BIAS | F_RELU | F_ROUND);
        int nA = BB * D2_ / 4;
        mcombine<<<(nA + 255) / 256, 256>>>(a, a, nA, nA);
    }
    // 12) x3 GEMM (splitK=8 -> part)
    {
        GDesc a = mkg(x2, mw3t, nullptr, part, BB, D3_, D2_, 0, 8, 0);
        mgemm<<<gctas(a), 256, GEMM_SMEM>>>(a, a, gctas(a));
    }
    // 13) fused x3 combine + final GEMV
    combine8_final<<<BB, 256>>>(part, mb3, mw4, mb4, out);
}